// round 13
// baseline (speedup 1.0000x reference)
#include <cuda_runtime.h>
#include <cuda_bf16.h>
#include <cstdint>
#include <cstddef>

#define NB 2
#define SL 2048
#define DM 2048
#define NH 16
#define DH 128
#define HIDN 5461
#define HIDP 5504
#define BSROWS (NB*SL)      // 4096
#define NCH 32
#define QST 8192            // packed qkvg row stride
#define FST 11008           // packed interleaved w1|w2 col count (64-blocks)

typedef __nv_bfloat16 bf16;

// ---------------- scratch ----------------
__device__ float g_qkvg[(size_t)BSROWS*QST];
__device__ float g_x1[(size_t)BSROWS*DM];
__device__ float g_st[(size_t)NB*NH*NCH*DH*DH];

__device__ __align__(16) bf16 g_h_hi [(size_t)BSROWS*DM];
__device__ __align__(16) bf16 g_h_lo [(size_t)BSROWS*DM];
__device__ __align__(16) bf16 g_h2_hi[(size_t)BSROWS*DM];
__device__ __align__(16) bf16 g_h2_lo[(size_t)BSROWS*DM];
__device__ __align__(16) bf16 g_a_hi [(size_t)BSROWS*DM];
__device__ __align__(16) bf16 g_a_lo [(size_t)BSROWS*DM];
__device__ __align__(16) bf16 g_fg_hi[(size_t)BSROWS*HIDP];
__device__ __align__(16) bf16 g_fg_lo[(size_t)BSROWS*HIDP];

__device__ __align__(16) bf16 g_wqkvg_hi[(size_t)DM*QST], g_wqkvg_lo[(size_t)DM*QST];
__device__ __align__(16) bf16 g_wo_hi[(size_t)DM*DM],  g_wo_lo[(size_t)DM*DM];
__device__ __align__(16) bf16 g_w12_hi[(size_t)DM*FST], g_w12_lo[(size_t)DM*FST];
__device__ __align__(16) bf16 g_w3_hi[(size_t)HIDP*DM], g_w3_lo[(size_t)HIDP*DM];

// ---------------- helpers ----------------
__device__ __forceinline__ unsigned f2tf(float x) {
    unsigned r;
    asm("cvt.rna.tf32.f32 %0, %1;" : "=r"(r) : "f"(x));
    return r;
}

__device__ __forceinline__ void split_bf16(float x, bf16& hi, bf16& lo) {
    hi = __float2bfloat16(x);
    lo = __float2bfloat16(x - __bfloat162float(hi));
}

__device__ __forceinline__ void split8_store(const float* v, bf16* hip, bf16* lop) {
    bf16 hh[8], ll[8];
#pragma unroll
    for (int j = 0; j < 8; j++) split_bf16(v[j], hh[j], ll[j]);
    *reinterpret_cast<uint4*>(hip) = *reinterpret_cast<uint4*>(hh);
    *reinterpret_cast<uint4*>(lop) = *reinterpret_cast<uint4*>(ll);
}

__device__ __forceinline__ void split4_store(const float* v, bf16* hip, bf16* lop) {
    bf16 hh[4], ll[4];
#pragma unroll
    for (int j = 0; j < 4; j++) split_bf16(v[j], hh[j], ll[j]);
    *reinterpret_cast<uint2*>(hip) = *reinterpret_cast<uint2*>(hh);
    *reinterpret_cast<uint2*>(lop) = *reinterpret_cast<uint2*>(ll);
}

__device__ __forceinline__ void mma8(float* c, const unsigned* a, const unsigned* b) {
    asm volatile(
        "mma.sync.aligned.m16n8k8.row.col.f32.tf32.tf32.f32 "
        "{%0,%1,%2,%3}, {%4,%5,%6,%7}, {%8,%9}, {%0,%1,%2,%3};\n"
        : "+f"(c[0]), "+f"(c[1]), "+f"(c[2]), "+f"(c[3])
        : "r"(a[0]), "r"(a[1]), "r"(a[2]), "r"(a[3]), "r"(b[0]), "r"(b[1]));
}

__device__ __forceinline__ void mma16(float* c, const unsigned* a, const unsigned* b) {
    asm volatile(
        "mma.sync.aligned.m16n8k16.row.col.f32.bf16.bf16.f32 "
        "{%0,%1,%2,%3}, {%4,%5,%6,%7}, {%8,%9}, {%0,%1,%2,%3};\n"
        : "+f"(c[0]), "+f"(c[1]), "+f"(c[2]), "+f"(c[3])
        : "r"(a[0]), "r"(a[1]), "r"(a[2]), "r"(a[3]), "r"(b[0]), "r"(b[1]));
}

__device__ __forceinline__ void ldsm4(unsigned* r, unsigned addr) {
    asm volatile("ldmatrix.sync.aligned.m8n8.x4.shared.b16 {%0,%1,%2,%3}, [%4];\n"
        : "=r"(r[0]), "=r"(r[1]), "=r"(r[2]), "=r"(r[3]) : "r"(addr));
}
__device__ __forceinline__ void ldsm4t(unsigned* r, unsigned addr) {
    asm volatile("ldmatrix.sync.aligned.m8n8.x4.trans.shared.b16 {%0,%1,%2,%3}, [%4];\n"
        : "=r"(r[0]), "=r"(r[1]), "=r"(r[2]), "=r"(r[3]) : "r"(addr));
}
__device__ __forceinline__ void cpa16(unsigned dst, const void* src) {
    asm volatile("cp.async.cg.shared.global [%0], [%1], 16;\n" :: "r"(dst), "l"(src));
}

// ---------------- weight packers ----------------
__global__ __launch_bounds__(256)
void conv_qkvg(const float* __restrict__ wq, const float* __restrict__ wk,
               const float* __restrict__ wv, const float* __restrict__ wg,
               bf16* __restrict__ hi, bf16* __restrict__ lo)
{
    const size_t n8 = (size_t)DM * QST / 8;
    size_t i = (size_t)blockIdx.x * 256 + threadIdx.x;
    const size_t st = (size_t)gridDim.x * 256;
    for (; i < n8; i += st) {
        size_t i8 = i * 8;
        size_t k = i8 >> 13;
        int c = (int)(i8 & (QST - 1));
        int proj = c >> 11, col = c & 2047;
        const float* s = (proj == 0) ? wq : (proj == 1) ? wk : (proj == 2) ? wv : wg;
        float v[8];
        *reinterpret_cast<float4*>(v)     = *reinterpret_cast<const float4*>(s + k * DM + col);
        *reinterpret_cast<float4*>(v + 4) = *reinterpret_cast<const float4*>(s + k * DM + col + 4);
        split8_store(v, hi + i8, lo + i8);
    }
}

__global__ __launch_bounds__(256)
void conv_wo(const float* __restrict__ src, bf16* __restrict__ hi, bf16* __restrict__ lo)
{
    const size_t n8 = (size_t)DM * DM / 8;
    size_t i = (size_t)blockIdx.x * 256 + threadIdx.x;
    const size_t st = (size_t)gridDim.x * 256;
    for (; i < n8; i += st) {
        size_t i8 = i * 8;
        float v[8];
        *reinterpret_cast<float4*>(v)     = *reinterpret_cast<const float4*>(src + i8);
        *reinterpret_cast<float4*>(v + 4) = *reinterpret_cast<const float4*>(src + i8 + 4);
        split8_store(v, hi + i8, lo + i8);
    }
}

// interleaved at 64-col granularity: 64-col blocks alternate w1/w2.
__global__ __launch_bounds__(256)
void conv_w12(const float* __restrict__ w1, const float* __restrict__ w2,
              bf16* __restrict__ hi, bf16* __restrict__ lo)
{
    const size_t n8 = (size_t)DM * FST / 8;
    size_t i = (size_t)blockIdx.x * 256 + threadIdx.x;
    const size_t st = (size_t)gridDim.x * 256;
    for (; i < n8; i += st) {
        size_t i8 = i * 8;
        size_t k = i8 / FST;
        int c = (int)(i8 - k * FST);
        int blk = c >> 6;
        int fcol = (blk >> 1) * 64 + (c & 63);
        const float* w = (blk & 1) ? w2 : w1;
        float v[8];
#pragma unroll
        for (int j = 0; j < 8; j++) {
            int col = fcol + j;
            v[j] = (col < HIDN) ? w[k * HIDN + col] : 0.f;
        }
        split8_store(v, hi + i8, lo + i8);
    }
}

__global__ __launch_bounds__(256)
void conv_w3(const float* __restrict__ w3, bf16* __restrict__ hi, bf16* __restrict__ lo)
{
    const size_t n8 = (size_t)HIDP * DM / 8;
    size_t i = (size_t)blockIdx.x * 256 + threadIdx.x;
    const size_t st = (size_t)gridDim.x * 256;
    for (; i < n8; i += st) {
        size_t i8 = i * 8;
        int r = (int)(i8 >> 11);
        float v[8];
        if (r < HIDN) {
            *reinterpret_cast<float4*>(v)     = *reinterpret_cast<const float4*>(w3 + i8);
            *reinterpret_cast<float4*>(v + 4) = *reinterpret_cast<const float4*>(w3 + i8 + 4);
        } else {
#pragma unroll
            for (int j = 0; j < 8; j++) v[j] = 0.f;
        }
        split8_store(v, hi + i8, lo + i8);
    }
}

// ---------------- LayerNorm -> bf16 hi/lo ----------------
__global__ __launch_bounds__(256)
void ln_kernel(const float* __restrict__ x, const float* __restrict__ w,
               const float* __restrict__ b, bf16* __restrict__ ohi,
               bf16* __restrict__ olo)
{
    __shared__ float red[16];
    const int row = blockIdx.x;
    const float* xr = x + (size_t)row * DM;
    float vals[8];
    float s = 0.f, ss = 0.f;
#pragma unroll
    for (int j = 0; j < 8; j++) {
        float v = xr[threadIdx.x + j * 256];
        vals[j] = v; s += v; ss += v * v;
    }
#pragma unroll
    for (int o = 16; o > 0; o >>= 1) {
        s  += __shfl_xor_sync(0xFFFFFFFFu, s,  o);
        ss += __shfl_xor_sync(0xFFFFFFFFu, ss, o);
    }
    const int warp = threadIdx.x >> 5, lane = threadIdx.x & 31;
    if (lane == 0) { red[warp] = s; red[8 + warp] = ss; }
    __syncthreads();
    s = 0.f; ss = 0.f;
#pragma unroll
    for (int k = 0; k < 8; k++) { s += red[k]; ss += red[8 + k]; }
    const float mean = s * (1.f / DM);
    const float var  = ss * (1.f / DM) - mean * mean;
    const float rstd = rsqrtf(var + 1e-5f);
#pragma unroll
    for (int j = 0; j < 8; j++) {
        int col = threadIdx.x + j * 256;
        float o = (vals[j] - mean) * rstd * w[col] + b[col];
        split_bf16(o, ohi[(size_t)row * DM + col], olo[(size_t)row * DM + col]);
    }
}

// ---------------- bf16x3 GEMM: CTA 128x128, 3-stage, 2 CTAs/SM ----------------
#define STG2_B 37888u
#define OFF2_AL 10240u
#define OFF2_BH 20480u
#define OFF2_BL 29184u
#define NSTG2 3u
#define GEMM2_SMEM (NSTG2*STG2_B)   // 113664 -> 2 CTAs = 227328 <= 228KB
#define EP2_LD 132                  // gated epilogue smem row stride (floats)

__device__ __forceinline__ void gemm2_prefetch(
    const bf16* __restrict__ Ahi, const bf16* __restrict__ Alo,
    const bf16* __restrict__ Bhi, const bf16* __restrict__ Blo,
    unsigned st, int bm, int bn, int k0, int K, int N, int tid)
{
#pragma unroll
    for (int i = 0; i < 2; i++) {
        int c = tid + i * 256;
        int row = c >> 2, chn = c & 3;
        size_t go = (size_t)(bm + row) * K + k0 + chn * 8;
        unsigned so = row * 80u + chn * 16u;
        cpa16(st + so, Ahi + go);
        cpa16(st + OFF2_AL + so, Alo + go);
    }
#pragma unroll
    for (int i = 0; i < 2; i++) {
        int c = tid + i * 256;
        int row = c >> 4, chn = c & 15;
        size_t go = (size_t)(k0 + row) * N + bn + chn * 8;
        unsigned so = row * 272u + chn * 16u;
        cpa16(st + OFF2_BH + so, Bhi + go);
        cpa16(st + OFF2_BL + so, Blo + go);
    }
    asm volatile("cp.async.commit_group;\n" ::: "memory");
}

__global__ __launch_bounds__(256, 2)
void gemm2_bf16x3(const bf16* __restrict__ Ahi, const bf16* __restrict__ Alo,
                  const bf16* __restrict__ Bhi, const bf16* __restrict__ Blo,
                  const float* __restrict__ Res, float* __restrict__ C,
                  bf16* __restrict__ Ghi, bf16* __restrict__ Glo,
                  int N, int K)
{
    extern __shared__ __align__(16) char smemraw[];
    const unsigned s0 = (unsigned)__cvta_generic_to_shared(smemraw);

    const int tid  = threadIdx.x;
    const int lane = tid & 31;
    const int warp = tid >> 5;
    const int wm = warp >> 2;     // 0..1 : 64 rows
    const int wn = warp & 3;      // 0..3 : 32 cols
    const int bm = blockIdx.y * 128;
    const int bn = blockIdx.x * 128;

    const unsigned laneA = (unsigned)(((lane & 7) + ((lane >> 3) & 1) * 8) * 80 + (lane >> 4) * 16);
    const unsigned laneB = (unsigned)(((lane & 7) + ((lane >> 3) & 1) * 8) * 272 + (lane >> 4) * 16);

    float acc[4][4][4];
#pragma unroll
    for (int a = 0; a < 4; a++)
#pragma unroll
        for (int b = 0; b < 4; b++)
#pragma unroll
            for (int c = 0; c < 4; c++) acc[a][b][c] = 0.f;

    const int nk = K >> 5;
    gemm2_prefetch(Ahi, Alo, Bhi, Blo, s0,           bm, bn, 0,  K, N, tid);
    gemm2_prefetch(Ahi, Alo, Bhi, Blo, s0 + STG2_B,  bm, bn, 32, K, N, tid);

    unsigned stage = 0;
    for (int t = 0; t < nk; t++) {
        if (t + 1 < nk) asm volatile("cp.async.wait_group 1;\n" ::: "memory");
        else            asm volatile("cp.async.wait_group 0;\n" ::: "memory");
        __syncthreads();

        if (t + 2 < nk) {
            unsigned nst = stage + 2u * STG2_B;
            if (nst >= NSTG2 * STG2_B) nst -= NSTG2 * STG2_B;
            gemm2_prefetch(Ahi, Alo, Bhi, Blo, s0 + nst, bm, bn, (t + 2) * 32, K, N, tid);
        }

        const unsigned st = s0 + stage;
        const unsigned aBase = st + (unsigned)(wm * 64 * 80) + laneA;
        const unsigned bBase = st + OFF2_BH + (unsigned)(wn * 32 * 2) + laneB;

#pragma unroll
        for (int ks = 0; ks < 2; ks++) {
            unsigned ah[4][4], al[4][4];
#pragma unroll
            for (int mt = 0; mt < 4; mt++) {
                unsigned ad = aBase + (unsigned)(mt * 16 * 80 + ks * 32);
                ldsm4(ah[mt], ad);
                ldsm4(al[mt], ad + OFF2_AL);
            }
#pragma unroll
            for (int p = 0; p < 2; p++) {
                unsigned bh[4], bl[4];
                unsigned bd = bBase + (unsigned)(ks * 16 * 272 + p * 32);
                ldsm4t(bh, bd);
                ldsm4t(bl, bd + (OFF2_BL - OFF2_BH));
#pragma unroll
                for (int mt = 0; mt < 4; mt++) {
                    mma16(acc[mt][2*p],   ah[mt], bh);
                    mma16(acc[mt][2*p],   ah[mt], bl);
                    mma16(acc[mt][2*p],   al[mt], bh);
                    mma16(acc[mt][2*p+1], ah[mt], bh + 2);
                    mma16(acc[mt][2*p+1], ah[mt], bl + 2);
                    mma16(acc[mt][2*p+1], al[mt], bh + 2);
                }
            }
        }
        stage += STG2_B;
        if (stage >= NSTG2 * STG2_B) stage = 0;
    }

    if (Ghi) {
        // gated epilogue: tile cols [0,64)=f1, [64,128)=f2 (same f-col range)
        __syncthreads();
        float* SM = reinterpret_cast<float*>(smemraw);
#pragma unroll
        for (int mt = 0; mt < 4; mt++)
#pragma unroll
            for (int nt = 0; nt < 4; nt++) {
                int r0 = wm * 64 + mt * 16 + (lane >> 2);
                int c0 = wn * 32 + nt * 8 + (lane & 3) * 2;
#pragma unroll
                for (int half = 0; half < 2; half++) {
                    int r = r0 + half * 8;
                    SM[r * EP2_LD + c0]     = acc[mt][nt][half * 2];
                    SM[r * EP2_LD + c0 + 1] = acc[mt][nt][half * 2 + 1];
                }
            }
        __syncthreads();
        const int fcol0 = blockIdx.x * 64;
#pragma unroll
        for (int j = 0; j < 4; j++) {
            int idx8 = (tid + j * 256) * 8;   // 128 rows x 64 f-cols
            int row = idx8 >> 6, c = idx8 & 63;
            const float* p1 = SM + row * EP2_LD + c;
            const float* p2 = p1 + 64;
            float v[8];
#pragma unroll
            for (int e = 0; e < 8; e++) {
                float a = p1[e];
                v[e] = (a / (1.f + expf(-a))) * p2[e];
            }
            size_t go = (size_t)(bm + row) * HIDP + fcol0 + c;
            split8_store(v, Ghi + go, Glo + go);
        }
    } else {
#pragma unroll
        for (int mt = 0; mt < 4; mt++)
#pragma unroll
            for (int nt = 0; nt < 4; nt++) {
                int r0 = bm + wm * 64 + mt * 16 + (lane >> 2);
                int c0 = bn + wn * 32 + nt * 8 + (lane & 3) * 2;
#pragma unroll
                for (int half = 0; half < 2; half++) {
                    int r = r0 + half * 8;
                    float2 v = make_float2(acc[mt][nt][half * 2], acc[mt][nt][half * 2 + 1]);
                    if (Res) {
                        float2 rv = *reinterpret_cast<const float2*>(&Res[(size_t)r * N + c0]);
                        v.x += rv.x; v.y += rv.y;
                    }
                    *reinterpret_cast<float2*>(&C[(size_t)r * N + c0]) = v;
                }
            }
    }
}

// ================= chunkwise retention =================
#define RC_SMEM ((128*68 + 64*136)*4)

__global__ __launch_bounds__(256, 1)
void ret_contrib(const float* __restrict__ K, const float* __restrict__ V,
                 float* __restrict__ CS)
{
    extern __shared__ float smc[];
    float* KsT = smc;
    float* Vs  = KsT + 128 * 68;

    const int tid  = threadIdx.x;
    const int lane = tid & 31;
    const int warp = tid >> 5;
    const int gq = lane >> 2;
    const int tg = lane & 3;
    const int wm = warp >> 2;
    const int wn = warp & 3;
    const int chunk = blockIdx.x;
    const int bh = blockIdx.y;
    const int b = bh >> 4, h = bh & 15;
    const int kb = chunk * 64;

    const float gamma = 1.f - exp2f(-5.f - (float)h);
    const float lg = log2f(gamma);
    const size_t rowbase = (size_t)(b * SL) * QST + (size_t)h * DH;

#pragma unroll
    for (int it = 0; it < 32; it++) {
        int idx = tid + it * 256;
        int t = idx >> 7, d = idx & 127;
        size_t gidx = rowbase + (size_t)(kb + t) * QST + d;
        float w = 0.08838834764831845f * exp2f((float)(63 - t) * lg);
        KsT[d * 68 + t] = __uint_as_float(f2tf(w * K[gidx]));
        Vs[t * 136 + d] = __uint_as_float(f2tf(V[gidx]));
    }
    __syncthreads();

    float acc[4][4][4];
#pragma unroll
    for (int a = 0; a < 4; a++)
#pragma unroll
        for (int bq = 0; bq < 4; bq++)
#pragma unroll
            for (int c = 0; c < 4; c++) acc[a][bq][c] = 0.f;

#pragma unroll
    for (int ks = 0; ks < 8; ks++) {
        const int kkk = ks * 8;
        unsigned af[4][4], bf[4][2];
#pragma unroll
        for (int mt = 0; mt < 4; mt++) {
            int m = wm * 64 + mt * 16 + gq;
            af[mt][0] = __float_as_uint(KsT[m * 68 + kkk + tg]);
            af[mt][1] = __float_as_uint(KsT[(m + 8) * 68 + kkk + tg]);
            af[mt][2] = __float_as_uint(KsT[m * 68 + kkk + tg + 4]);
            af[mt][3] = __float_as_uint(KsT[(m + 8) * 68 + kkk + tg + 4]);
        }
#pragma unroll
        for (int nt = 0; nt < 4; nt++) {
            int n = wn * 32 + nt * 8 + gq;
            bf[nt][0] = __float_as_uint(Vs[(kkk + tg) * 136 + n]);
            bf[nt][1] = __float_as_uint(Vs[(kkk + tg + 4) * 136 + n]);
        }
#pragma unroll
        for (int mt = 0; mt < 4; mt++)
#pragma unroll
            for (int nt = 0; nt < 4; nt++)
                mma8(acc[mt][nt], af[mt], bf[nt]);
    }

    float* outp = CS + ((size_t)bh * NCH + chunk) * (DH * DH);
#pragma unroll
    for (int mt = 0; mt < 4; mt++)
#pragma unroll
        for (int nt = 0; nt < 4; nt++) {
            int r0 = wm * 64 + mt * 16 + gq;
            int c0 = wn * 32 + nt * 8 + tg * 2;
#pragma unroll
            for (int e = 0; e < 4; e++) {
                int r = r0 + (e >> 1) * 8;
                int c = c0 + (e & 1);
                outp[r * DH + c] = acc[mt][nt][e];
            }
        }
}

__global__ __launch_bounds__(512)
void ret_scan(float* __restrict__ CS)
{
    const int bh = blockIdx.x;
    const int h = bh & 15;
    const float gamma = 1.f - exp2f(-5.f - (float)h);
    const float dec = exp2f(64.f * log2f(gamma));
    float* base = CS + (size_t)bh * NCH * (DH * DH);
    const int tid = threadIdx.x;

    float s[32];
#pragma unroll
    for (int j = 0; j < 32; j++) s[j] = 0.f;
    for (int i = 0; i < NCH; i++) {
        float* p = base + (size_t)i * (DH * DH);
#pragma unroll
        for (int j = 0; j < 32; j++) {
            int e = tid + j * 512;
            float c = p[e];
            p[e] = s[j];
            s[j] = s[j] * dec + c;
        }
    }
}

// ret_out with fused per-head GroupNorm + silu gate epilogue -> a_hi/a_lo (bf16)
#define RO_SMEM ((64*132*2 + 64*136 + 64*68 + 128*136 + 128 + 64)*4)

__global__ __launch_bounds__(256, 1)
void ret_out(const float* __restrict__ Q, const float* __restrict__ Kt,
             const float* __restrict__ V, const float* __restrict__ CS,
             const float* __restrict__ QKVG,
             bf16* __restrict__ Ahi, bf16* __restrict__ Alo)
{
    extern __shared__ float smr[];
    float* Qs  = smr;                // [64][132] (reused as output stage)
    float* Ks  = Qs + 64 * 132;
    float* Vs  = Ks + 64 * 132;
    float* Ss  = Vs + 64 * 136;
    float* Sts = Ss + 64 * 68;
    float* dp  = Sts + 128 * 136;
    float* dp2 = dp + 128;

    const int tid  = threadIdx.x;
    const int lane = tid & 31;
    const int warp = tid >> 5;
    const int gq = lane >> 2;
    const int tg = lane & 3;
    const int wm = warp >> 2;
    const int wn = warp & 3;
    const int chunk = blockIdx.x;
    const int bh = blockIdx.y;
    const int b = bh >> 4, h = bh & 15;
    const int qb = chunk * 64;

    const float gamma = 1.f - exp2f(-5.f - (float)h);
    const float lg = log2f(gamma);
    const size_t rowbase = (size_t)(b * SL) * QST + (size_t)h * DH;
    const float* stp = CS + ((size_t)bh * NCH + chunk) * (DH * DH);

#pragma unroll
    for (int it = 0; it < 32; it++) {
        int idx = tid + it * 256;
        int r = idx >> 7, d = idx & 127;
        size_t gidx = rowbase + (size_t)(qb + r) * QST + d;
        Qs[r * 132 + d] = __uint_as_float(f2tf(Q[gidx]));
        Ks[r * 132 + d] = __uint_as_float(f2tf(Kt[gidx]));
        Vs[r * 136 + d] = __uint_as_float(f2tf(V[gidx]));
    }
#pragma unroll
    for (int it = 0; it < 64; it++) {
        int idx = tid + it * 256;
        int r = idx >> 7, d = idx & 127;
        Sts[r * 136 + d] = __uint_as_float(f2tf(stp[idx]));
    }
    if (tid < 128) {
        int e = tid - 63;
        dp[tid] = (e < 0) ? 0.f : 0.08838834764831845f * exp2f((float)e * lg);
    }
    if (tid < 64) dp2[tid] = exp2f((float)(tid + 1) * lg);
    __syncthreads();

    float acco[2][4][4];
#pragma unroll
    for (int a = 0; a < 2; a++)
#pragma unroll
        for (int bq = 0; bq < 4; bq++)
#pragma unroll
            for (int c = 0; c < 4; c++) acco[a][bq][c] = 0.f;

#pragma unroll
    for (int ks = 0; ks < 16; ks++) {
        const int kkk = ks * 8;
        unsigned af[2][4], bf[4][2];
#pragma unroll
        for (int mt = 0; mt < 2; mt++) {
            int m = wm * 32 + mt * 16 + gq;
            af[mt][0] = __float_as_uint(Qs[m * 132 + kkk + tg]);
            af[mt][1] = __float_as_uint(Qs[(m + 8) * 132 + kkk + tg]);
            af[mt][2] = __float_as_uint(Qs[m * 132 + kkk + tg + 4]);
            af[mt][3] = __float_as_uint(Qs[(m + 8) * 132 + kkk + tg + 4]);
        }
#pragma unroll
        for (int nt = 0; nt < 4; nt++) {
            int n = wn * 32 + nt * 8 + gq;
            bf[nt][0] = __float_as_uint(Sts[(kkk + tg) * 136 + n]);
            bf[nt][1] = __float_as_uint(Sts[(kkk + tg + 4) * 136 + n]);
        }
#pragma unroll
        for (int mt = 0; mt < 2; mt++)
#pragma unroll
            for (int nt = 0; nt < 4; nt++)
                mma8(acco[mt][nt], af[mt], bf[nt]);
    }
#pragma unroll
    for (int mt = 0; mt < 2; mt++) {
        int r0 = wm * 32 + mt * 16 + gq;
        float sc0 = dp2[r0], sc1 = dp2[r0 + 8];
#pragma unroll
        for (int nt = 0; nt < 4; nt++) {
            acco[mt][nt][0] *= sc0; acco[mt][nt][1] *= sc0;
            acco[mt][nt][2] *= sc1; acco[mt][nt][3] *= sc1;
        }
    }

    float accs[2][2][4];
#pragma unroll
    for (int a = 0; a < 2; a++)
#pragma unroll
        for (int bq = 0; bq < 2; bq++)
#pragma unroll
            for (int c = 0; c < 4; c++) accs[a][bq][c] = 0.f;
#pragma unroll
    for (int ks = 0; ks < 16; ks++) {
        const int kkk = ks * 8;
        unsigned af[2][4], bf[2][2];
#pragma unroll
        for (int mt = 0; mt < 2; mt++) {
            int m = wm * 32 + mt * 16 + gq;
            af[mt][0] = __float_as_uint(Qs[m * 132 + kkk + tg]);
            af[mt][1] = __float_as_uint(Qs[(m + 8) * 132 + kkk + tg]);
            af[mt][2] = __float_as_uint(Qs[m * 132 + kkk + tg + 4]);
            af[mt][3] = __float_as_uint(Qs[(m + 8) * 132 + kkk + tg + 4]);
        }
#pragma unroll
        for (int nt = 0; nt < 2; nt++) {
            int n = wn * 16 + nt * 8 + gq;
            bf[nt][0] = __float_as_uint(Ks[n * 132 + kkk + tg]);
            bf[nt][1] = __float_as_uint(Ks[n * 132 + kkk + tg + 4]);
        }
#pragma unroll
        for (int mt = 0; mt < 2; mt++)
#pragma unroll
            for (int nt = 0; nt < 2; nt++)
                mma8(accs[mt][nt], af[mt], bf[nt]);
    }
#pragma unroll
    for (int mt = 0; mt < 2; mt++)
#pragma unroll
        for (int nt = 0; nt < 2; nt++) {
            int sr0 = wm * 32 + mt * 16 + gq;
            int tc0 = wn * 16 + nt * 8 + tg * 2;
#pragma unroll
            for (int e = 0; e < 4; e++) {
                int sr = sr0 + (e >> 1) * 8;
                int tc = tc0 + (e & 1);
                float coeff = dp[sr - tc + 63];
                Ss[sr * 68 + tc] = __uint_as_float(f2tf(accs[mt][nt][e] * coeff));
            }
        }
    __syncthreads();

#pragma unroll
    for (int ks = 0; ks < 8; ks++) {
        const int kkk = ks * 8;
        unsigned af[2][4], bf[4][2];
#pragma unroll
        for (int mt = 0; mt < 2; mt++) {
            int m = wm * 32 + mt * 16 + gq;
            af[mt][0] = __float_as_uint(Ss[m * 68 + kkk + tg]);
            af[mt][1] = __float_as_uint(Ss[(m + 8) * 68 + kkk + tg]);
            af[mt][2] = __float_as_uint(Ss[m * 68 + kkk + tg + 4]);
            af[mt][3] = __float_as_uint(Ss[(m + 8) * 68 + kkk + tg + 4]);
        }
#pragma unroll
        for (int nt = 0; nt < 4; nt++) {
            int n = wn * 32 + nt * 8 + gq;
            bf[nt][0] = __float_as_uint(Vs[(kkk + tg) * 136 + n]);
            bf[nt][1] = __float_as_uint(Vs[(kkk + tg + 4) * 136 + n]);
        }
#pragma unroll
        for (int mt = 0; mt < 2; mt++)
#pragma unroll
            for (int nt = 0; nt < 4; nt++)
                mma8(acco[mt][nt], af[mt], bf[nt]);
    }

    // ---- fused epilogue: stage to smem, per-row groupnorm + silu gate -> bf16 hi/lo
    __syncthreads();   // all warps done reading Qs (OS aliases Qs)
    float* OS = Qs;    // [64][132]
#pragma unroll
    for (int mt = 0; mt < 2; mt++)
#pragma unroll
        for (int nt = 0; nt < 4; nt++) {
            int r0 = wm * 32 + mt * 16 + gq;
            int c0 = wn * 32 + nt * 8 + tg * 2;
#pragma unroll
            for (int e = 0; e < 4; e++) {
                int r = r0 + (e >> 1) * 8;
                int c = c0 + (e & 1);
                OS[r * 132 + c] = acco[mt][nt][e];
            }
        }
    __syncthreads();

#pragma unroll
    for (int i = 0; i < 8; i++) {
        int row = warp + i * 8;       // local row 0..63, one warp per row
        float4 v = *reinterpret_cast<const float4*>(OS + row * 132 + lane * 4);
        float s  = v.x + v.y + v.z + v.w;
        float ss = v.x*v.x + v.y*v.y + v.z*v.z + v.w*v.w;
#pragma unroll
        for (int o = 16; o > 0; o >>= 1) {
            s  += __shfl_xor_sync(0xFFFFFFFFu, s,  o);
            ss += __shfl_xor_sync(0xFFFFFFFFu, ss, o);
        }
        const float mean = s * (1.f / DH);
        const float var  = ss * (1.f / DH) - mean * mean;
        const float rstd = rsqrtf(var + 1e-5f);
        const int grow = b * SL + qb + row;
        float4 gv = *reinterpret_cast<const float4*>(
            QKVG + (size_t)grow * QST + 6144 + h * DH + lane * 4);
        float outv[4];
        outv[0] = (gv.x / (1.f + expf(-gv.x))) * ((v.x - mean) * rstd);
        outv[1] = (gv.y / (1.f + expf(-gv.y))) * ((v.y - mean) * rstd);
        outv[2] = (gv.z / (1.f + expf(-gv.z))) * ((v.z - mean) * rstd);
        outv[3] = (gv.w / (1.f + expf(-gv.w))) * ((v.w - mean) * rstd);
        size_t ab = (size_t)grow * DM + h * DH + lane * 4;
        split4_store(outv, Ahi + ab, Alo + ab);
    }
}

// ---------------- launch ----------------
extern "C" void kernel_launch(void* const* d_in, const int* in_sizes, int n_in,
                              void* d_out, int out_size)
{
    const float* x   = (const float*)d_in[0];
    const float* n1w = (const float*)d_in[1];
    const float* n1b = (const float*)d_in[2];
    const float* wq  = (const float*)d_in[3];
    const float* wk  = (const float*)d_in[4];
    const float* wv  = (const float*)d_in[5];
    const float* wg  = (const float*)d_in[6];
    const float* wo  = (const float*)d_in[7];
    const float* n2w = (const float*)d_in[8];
    const float* n2b = (const float*)d_in[9];
    const float* w1  = (const float*)d_in[10];
    const float* w2  = (const float*)d_in[11];
    const float* w3  = (const float*)d_in[12];
    float* out = (float*)d_out;

    float *qkvg, *x1, *cs;
    bf16 *h_hi, *h_lo, *h2_hi, *h2_lo, *a_hi, *a_lo, *fg_hi, *fg_lo;
    bf16 *wp_hi, *wp_lo, *wo_hi, *wo_lo, *w12_hi, *w12_lo, *w3_hi, *w3_lo;

    cudaGetSymbolAddress((void**)&qkvg, g_qkvg);
    cudaGetSymbolAddress((void**)&x1,   g_x1);
    cudaGetSymbolAddress((void**)&cs,   g_st);
    cudaGetSymbolAddress((void**)&h_hi,  g_h_hi);
    cudaGetSymbolAddress((void**)&h_lo,  g_h_lo);
    cudaGetSymbolAddress((void**)&h2_hi, g_h2_hi);
    cudaGetSymbolAddress((void**)&h2_lo, g_h2_lo);
    cudaGetSymbolAddress((void**)&a_hi,  g_a_hi);
    cudaGetSymbolAddress((void**)&a_lo,  g_a_lo);
    cudaGetSymbolAddress((void**)&fg_hi, g_fg_hi);
    cudaGetSymbolAddress((void**)&fg_lo, g_fg_lo);
    cudaGetSymbolAddress((void**)&wp_hi,  g_wqkvg_hi); cudaGetSymbolAddress((void**)&wp_lo,  g_wqkvg_lo);
    cudaGetSymbolAddress((void**)&wo_hi,  g_wo_hi);    cudaGetSymbolAddress((void**)&wo_lo,  g_wo_lo);
    cudaGetSymbolAddress((void**)&w12_hi, g_w12_hi);   cudaGetSymbolAddress((void**)&w12_lo, g_w12_lo);
    cudaGetSymbolAddress((void**)&w3_hi,  g_w3_hi);    cudaGetSymbolAddress((void**)&w3_lo,  g_w3_lo);

    cudaFuncSetAttribute((const void*)gemm2_bf16x3,
                         cudaFuncAttributeMaxDynamicSharedMemorySize, GEMM2_SMEM);
    cudaFuncSetAttribute((const void*)ret_contrib,
                         cudaFuncAttributeMaxDynamicSharedMemorySize, RC_SMEM);
    cudaFuncSetAttribute((const void*)ret_out,
                         cudaFuncAttributeMaxDynamicSharedMemorySize, RO_SMEM);

    // positions 1-3
    conv_qkvg<<<4096, 256>>>(wq, wk, wv, wg, wp_hi, wp_lo);
    conv_wo<<<2048, 256>>>(wo, wo_hi, wo_lo);
    ln_kernel<<<BSROWS, 256>>>(x, n1w, n1b, h_hi, h_lo);

    // position 4: qkvg GEMM (ncu capture target)
    gemm2_bf16x3<<<dim3(QST / 128, BSROWS / 128), 256, GEMM2_SMEM>>>(
        h_hi, h_lo, wp_hi, wp_lo, nullptr, qkvg, nullptr, nullptr, QST, DM);

    conv_w12<<<4096, 256>>>(w1, w2, w12_hi, w12_lo);
    conv_w3<<<2048, 256>>>(w3, w3_hi, w3_lo);

    ret_contrib<<<dim3(NCH, NB * NH), 256, RC_SMEM>>>(qkvg + 2048, qkvg + 4096, cs);
    ret_scan<<<NB * NH, 512>>>(cs);
    // fused retention-out + groupnorm + silu gate -> a_hi/a_lo
    ret_out<<<dim3(NCH, NB * NH), 256, RO_SMEM>>>(
        qkvg, qkvg + 2048, qkvg + 4096, cs, qkvg, a_hi, a_lo);

    gemm2_bf16x3<<<dim3(DM / 128, BSROWS / 128), 256, GEMM2_SMEM>>>(
        a_hi, a_lo, wo_hi, wo_lo, x, x1, nullptr, nullptr, DM, DM);

    ln_kernel<<<BSROWS, 256>>>(x1, n2w, n2b, h2_hi, h2_lo);

    // w12 GEMM with fused silu-gate epilogue (64-col interleave) -> fg
    gemm2_bf16x3<<<dim3(FST / 128, BSROWS / 128), 256, GEMM2_SMEM>>>(
        h2_hi, h2_lo, w12_hi, w12_lo, nullptr, nullptr, fg_hi, fg_lo, FST, DM);

    gemm2_bf16x3<<<dim3(DM / 128, BSROWS / 128), 256, GEMM2_SMEM>>>(
        fg_hi, fg_lo, w3_hi, w3_lo, x1, out, nullptr, nullptr, DM, HIDP);
}

// round 14
// speedup vs baseline: 1.0325x; 1.0325x over previous
#include <cuda_runtime.h>
#include <cuda_bf16.h>
#include <cstdint>
#include <cstddef>

#define NB 2
#define SL 2048
#define DM 2048
#define NH 16
#define DH 128
#define HIDN 5461
#define HIDP 5504
#define BSROWS (NB*SL)      // 4096
#define NCH 32
#define QST 8192            // packed qkvg row stride
#define FST 11008           // packed interleaved w1|w2 col count (64-blocks)

typedef __nv_bfloat16 bf16;

// ---------------- scratch ----------------
__device__ float g_qkvg[(size_t)BSROWS*QST];
__device__ float g_x1[(size_t)BSROWS*DM];
__device__ float g_st[(size_t)NB*NH*NCH*DH*DH];

__device__ __align__(16) bf16 g_h_hi [(size_t)BSROWS*DM];
__device__ __align__(16) bf16 g_h_lo [(size_t)BSROWS*DM];
__device__ __align__(16) bf16 g_h2_hi[(size_t)BSROWS*DM];
__device__ __align__(16) bf16 g_h2_lo[(size_t)BSROWS*DM];
__device__ __align__(16) bf16 g_a_hi [(size_t)BSROWS*DM];
__device__ __align__(16) bf16 g_a_lo [(size_t)BSROWS*DM];
__device__ __align__(16) bf16 g_fg_hi[(size_t)BSROWS*HIDP];
__device__ __align__(16) bf16 g_fg_lo[(size_t)BSROWS*HIDP];

__device__ __align__(16) bf16 g_wqkvg_hi[(size_t)DM*QST], g_wqkvg_lo[(size_t)DM*QST];
__device__ __align__(16) bf16 g_wo_hi[(size_t)DM*DM],  g_wo_lo[(size_t)DM*DM];
__device__ __align__(16) bf16 g_w12_hi[(size_t)DM*FST], g_w12_lo[(size_t)DM*FST];
__device__ __align__(16) bf16 g_w3_hi[(size_t)HIDP*DM], g_w3_lo[(size_t)HIDP*DM];

// ---------------- helpers ----------------
__device__ __forceinline__ unsigned f2tf(float x) {
    unsigned r;
    asm("cvt.rna.tf32.f32 %0, %1;" : "=r"(r) : "f"(x));
    return r;
}

__device__ __forceinline__ void split_bf16(float x, bf16& hi, bf16& lo) {
    hi = __float2bfloat16(x);
    lo = __float2bfloat16(x - __bfloat162float(hi));
}

__device__ __forceinline__ void split8_store(const float* v, bf16* hip, bf16* lop) {
    bf16 hh[8], ll[8];
#pragma unroll
    for (int j = 0; j < 8; j++) split_bf16(v[j], hh[j], ll[j]);
    *reinterpret_cast<uint4*>(hip) = *reinterpret_cast<uint4*>(hh);
    *reinterpret_cast<uint4*>(lop) = *reinterpret_cast<uint4*>(ll);
}

__device__ __forceinline__ void split4_store(const float* v, bf16* hip, bf16* lop) {
    bf16 hh[4], ll[4];
#pragma unroll
    for (int j = 0; j < 4; j++) split_bf16(v[j], hh[j], ll[j]);
    *reinterpret_cast<uint2*>(hip) = *reinterpret_cast<uint2*>(hh);
    *reinterpret_cast<uint2*>(lop) = *reinterpret_cast<uint2*>(ll);
}

__device__ __forceinline__ void mma8(float* c, const unsigned* a, const unsigned* b) {
    asm volatile(
        "mma.sync.aligned.m16n8k8.row.col.f32.tf32.tf32.f32 "
        "{%0,%1,%2,%3}, {%4,%5,%6,%7}, {%8,%9}, {%0,%1,%2,%3};\n"
        : "+f"(c[0]), "+f"(c[1]), "+f"(c[2]), "+f"(c[3])
        : "r"(a[0]), "r"(a[1]), "r"(a[2]), "r"(a[3]), "r"(b[0]), "r"(b[1]));
}

__device__ __forceinline__ void mma16(float* c, const unsigned* a, const unsigned* b) {
    asm volatile(
        "mma.sync.aligned.m16n8k16.row.col.f32.bf16.bf16.f32 "
        "{%0,%1,%2,%3}, {%4,%5,%6,%7}, {%8,%9}, {%0,%1,%2,%3};\n"
        : "+f"(c[0]), "+f"(c[1]), "+f"(c[2]), "+f"(c[3])
        : "r"(a[0]), "r"(a[1]), "r"(a[2]), "r"(a[3]), "r"(b[0]), "r"(b[1]));
}

__device__ __forceinline__ void ldsm4(unsigned* r, unsigned addr) {
    asm volatile("ldmatrix.sync.aligned.m8n8.x4.shared.b16 {%0,%1,%2,%3}, [%4];\n"
        : "=r"(r[0]), "=r"(r[1]), "=r"(r[2]), "=r"(r[3]) : "r"(addr));
}
__device__ __forceinline__ void ldsm4t(unsigned* r, unsigned addr) {
    asm volatile("ldmatrix.sync.aligned.m8n8.x4.trans.shared.b16 {%0,%1,%2,%3}, [%4];\n"
        : "=r"(r[0]), "=r"(r[1]), "=r"(r[2]), "=r"(r[3]) : "r"(addr));
}
__device__ __forceinline__ void cpa16(unsigned dst, const void* src) {
    asm volatile("cp.async.cg.shared.global [%0], [%1], 16;\n" :: "r"(dst), "l"(src));
}

// ---------------- weight packers ----------------
__global__ __launch_bounds__(256)
void conv_qkvg(const float* __restrict__ wq, const float* __restrict__ wk,
               const float* __restrict__ wv, const float* __restrict__ wg,
               bf16* __restrict__ hi, bf16* __restrict__ lo)
{
    const size_t n8 = (size_t)DM * QST / 8;
    size_t i = (size_t)blockIdx.x * 256 + threadIdx.x;
    const size_t st = (size_t)gridDim.x * 256;
    for (; i < n8; i += st) {
        size_t i8 = i * 8;
        size_t k = i8 >> 13;
        int c = (int)(i8 & (QST - 1));
        int proj = c >> 11, col = c & 2047;
        const float* s = (proj == 0) ? wq : (proj == 1) ? wk : (proj == 2) ? wv : wg;
        float v[8];
        *reinterpret_cast<float4*>(v)     = *reinterpret_cast<const float4*>(s + k * DM + col);
        *reinterpret_cast<float4*>(v + 4) = *reinterpret_cast<const float4*>(s + k * DM + col + 4);
        split8_store(v, hi + i8, lo + i8);
    }
}

__global__ __launch_bounds__(256)
void conv_wo(const float* __restrict__ src, bf16* __restrict__ hi, bf16* __restrict__ lo)
{
    const size_t n8 = (size_t)DM * DM / 8;
    size_t i = (size_t)blockIdx.x * 256 + threadIdx.x;
    const size_t st = (size_t)gridDim.x * 256;
    for (; i < n8; i += st) {
        size_t i8 = i * 8;
        float v[8];
        *reinterpret_cast<float4*>(v)     = *reinterpret_cast<const float4*>(src + i8);
        *reinterpret_cast<float4*>(v + 4) = *reinterpret_cast<const float4*>(src + i8 + 4);
        split8_store(v, hi + i8, lo + i8);
    }
}

// interleaved at 64-col granularity: 64-col blocks alternate w1/w2.
__global__ __launch_bounds__(256)
void conv_w12(const float* __restrict__ w1, const float* __restrict__ w2,
              bf16* __restrict__ hi, bf16* __restrict__ lo)
{
    const size_t n8 = (size_t)DM * FST / 8;
    size_t i = (size_t)blockIdx.x * 256 + threadIdx.x;
    const size_t st = (size_t)gridDim.x * 256;
    for (; i < n8; i += st) {
        size_t i8 = i * 8;
        size_t k = i8 / FST;
        int c = (int)(i8 - k * FST);
        int blk = c >> 6;
        int fcol = (blk >> 1) * 64 + (c & 63);
        const float* w = (blk & 1) ? w2 : w1;
        float v[8];
#pragma unroll
        for (int j = 0; j < 8; j++) {
            int col = fcol + j;
            v[j] = (col < HIDN) ? w[k * HIDN + col] : 0.f;
        }
        split8_store(v, hi + i8, lo + i8);
    }
}

__global__ __launch_bounds__(256)
void conv_w3(const float* __restrict__ w3, bf16* __restrict__ hi, bf16* __restrict__ lo)
{
    const size_t n8 = (size_t)HIDP * DM / 8;
    size_t i = (size_t)blockIdx.x * 256 + threadIdx.x;
    const size_t st = (size_t)gridDim.x * 256;
    for (; i < n8; i += st) {
        size_t i8 = i * 8;
        int r = (int)(i8 >> 11);
        float v[8];
        if (r < HIDN) {
            *reinterpret_cast<float4*>(v)     = *reinterpret_cast<const float4*>(w3 + i8);
            *reinterpret_cast<float4*>(v + 4) = *reinterpret_cast<const float4*>(w3 + i8 + 4);
        } else {
#pragma unroll
            for (int j = 0; j < 8; j++) v[j] = 0.f;
        }
        split8_store(v, hi + i8, lo + i8);
    }
}

// ---------------- LayerNorm -> bf16 hi/lo ----------------
__global__ __launch_bounds__(256)
void ln_kernel(const float* __restrict__ x, const float* __restrict__ w,
               const float* __restrict__ b, bf16* __restrict__ ohi,
               bf16* __restrict__ olo)
{
    __shared__ float red[16];
    const int row = blockIdx.x;
    const float* xr = x + (size_t)row * DM;
    float vals[8];
    float s = 0.f, ss = 0.f;
#pragma unroll
    for (int j = 0; j < 8; j++) {
        float v = xr[threadIdx.x + j * 256];
        vals[j] = v; s += v; ss += v * v;
    }
#pragma unroll
    for (int o = 16; o > 0; o >>= 1) {
        s  += __shfl_xor_sync(0xFFFFFFFFu, s,  o);
        ss += __shfl_xor_sync(0xFFFFFFFFu, ss, o);
    }
    const int warp = threadIdx.x >> 5, lane = threadIdx.x & 31;
    if (lane == 0) { red[warp] = s; red[8 + warp] = ss; }
    __syncthreads();
    s = 0.f; ss = 0.f;
#pragma unroll
    for (int k = 0; k < 8; k++) { s += red[k]; ss += red[8 + k]; }
    const float mean = s * (1.f / DM);
    const float var  = ss * (1.f / DM) - mean * mean;
    const float rstd = rsqrtf(var + 1e-5f);
#pragma unroll
    for (int j = 0; j < 8; j++) {
        int col = threadIdx.x + j * 256;
        float o = (vals[j] - mean) * rstd * w[col] + b[col];
        split_bf16(o, ohi[(size_t)row * DM + col], olo[(size_t)row * DM + col]);
    }
}

// ---------------- bf16x3 GEMM: CTA 128x128, 3-stage, 2 CTAs/SM ----------------
#define STG2_B 37888u
#define OFF2_AL 10240u
#define OFF2_BH 20480u
#define OFF2_BL 29184u
#define NSTG2 3u
#define GEMM2_SMEM (NSTG2*STG2_B)   // 113664 -> 2 CTAs = 227328 <= 228KB
#define EP2_LD 132                  // gated epilogue smem row stride (floats)

__global__ __launch_bounds__(256, 2)
void gemm2_bf16x3(const bf16* __restrict__ Ahi, const bf16* __restrict__ Alo,
                  const bf16* __restrict__ Bhi, const bf16* __restrict__ Blo,
                  const float* __restrict__ Res, float* __restrict__ C,
                  bf16* __restrict__ Ghi, bf16* __restrict__ Glo,
                  int N, int K)
{
    extern __shared__ __align__(16) char smemraw[];
    const unsigned s0 = (unsigned)__cvta_generic_to_shared(smemraw);

    const int tid  = threadIdx.x;
    const int lane = tid & 31;
    const int warp = tid >> 5;
    const int wm = warp >> 2;     // 0..1 : 64 rows
    const int wn = warp & 3;      // 0..3 : 32 cols
    const int bm = blockIdx.y * 128;
    const int bn = blockIdx.x * 128;

    // pointer-increment prefetch state (computed once)
    const int arow = tid >> 2, achn = tid & 3;
    const int brow = tid >> 4, bchn = tid & 15;
    const bf16* pAh = Ahi + (size_t)(bm + arow) * K + achn * 8;
    const bf16* pAl = Alo + (size_t)(bm + arow) * K + achn * 8;
    const bf16* pBh = Bhi + (size_t)brow * N + bn + bchn * 8;
    const bf16* pBl = Blo + (size_t)brow * N + bn + bchn * 8;
    const size_t aStep = 64 * (size_t)K;    // second A chunk (row +64)
    const size_t bStep = 16 * (size_t)N;    // second B chunk (row +16)
    const size_t bAdv  = 32 * (size_t)N;    // per-stage B advance
    const unsigned soA = (unsigned)(arow * 80 + achn * 16);
    const unsigned soB = (unsigned)(brow * 272 + bchn * 16);

#define G2_PREFETCH(stg)                                           \
    do {                                                           \
        unsigned _s = (stg);                                       \
        cpa16(_s + soA,              pAh);                         \
        cpa16(_s + soA + 5120u,      pAh + aStep);                 \
        cpa16(_s + OFF2_AL + soA,         pAl);                    \
        cpa16(_s + OFF2_AL + soA + 5120u, pAl + aStep);            \
        cpa16(_s + OFF2_BH + soB,         pBh);                    \
        cpa16(_s + OFF2_BH + soB + 4352u, pBh + bStep);            \
        cpa16(_s + OFF2_BL + soB,         pBl);                    \
        cpa16(_s + OFF2_BL + soB + 4352u, pBl + bStep);            \
        asm volatile("cp.async.commit_group;\n" ::: "memory");     \
        pAh += 32; pAl += 32; pBh += bAdv; pBl += bAdv;            \
    } while (0)

    const unsigned laneA = (unsigned)(((lane & 7) + ((lane >> 3) & 1) * 8) * 80 + (lane >> 4) * 16);
    const unsigned laneB = (unsigned)(((lane & 7) + ((lane >> 3) & 1) * 8) * 272 + (lane >> 4) * 16);

    float acc[4][4][4];
#pragma unroll
    for (int a = 0; a < 4; a++)
#pragma unroll
        for (int b = 0; b < 4; b++)
#pragma unroll
            for (int c = 0; c < 4; c++) acc[a][b][c] = 0.f;

    const int nk = K >> 5;
    G2_PREFETCH(s0);
    G2_PREFETCH(s0 + STG2_B);

    unsigned stage = 0;
    for (int t = 0; t < nk; t++) {
        if (t + 1 < nk) asm volatile("cp.async.wait_group 1;\n" ::: "memory");
        else            asm volatile("cp.async.wait_group 0;\n" ::: "memory");
        __syncthreads();

        if (t + 2 < nk) {
            unsigned nst = stage + 2u * STG2_B;
            if (nst >= NSTG2 * STG2_B) nst -= NSTG2 * STG2_B;
            G2_PREFETCH(s0 + nst);
        }

        const unsigned st = s0 + stage;
        const unsigned aBase = st + (unsigned)(wm * 64 * 80) + laneA;
        const unsigned bBase = st + OFF2_BH + (unsigned)(wn * 32 * 2) + laneB;

#pragma unroll
        for (int ks = 0; ks < 2; ks++) {
            unsigned ah[4][4], al[4][4];
#pragma unroll
            for (int mt = 0; mt < 4; mt++) {
                unsigned ad = aBase + (unsigned)(mt * 16 * 80 + ks * 32);
                ldsm4(ah[mt], ad);
                ldsm4(al[mt], ad + OFF2_AL);
            }
#pragma unroll
            for (int p = 0; p < 2; p++) {
                unsigned bh[4], bl[4];
                unsigned bd = bBase + (unsigned)(ks * 16 * 272 + p * 32);
                ldsm4t(bh, bd);
                ldsm4t(bl, bd + (OFF2_BL - OFF2_BH));
#pragma unroll
                for (int mt = 0; mt < 4; mt++) {
                    mma16(acc[mt][2*p],   ah[mt], bh);
                    mma16(acc[mt][2*p],   ah[mt], bl);
                    mma16(acc[mt][2*p],   al[mt], bh);
                    mma16(acc[mt][2*p+1], ah[mt], bh + 2);
                    mma16(acc[mt][2*p+1], ah[mt], bl + 2);
                    mma16(acc[mt][2*p+1], al[mt], bh + 2);
                }
            }
        }
        stage += STG2_B;
        if (stage >= NSTG2 * STG2_B) stage = 0;
    }
#undef G2_PREFETCH

    if (Ghi) {
        // gated epilogue: tile cols [0,64)=f1, [64,128)=f2 (same f-col range)
        __syncthreads();
        float* SM = reinterpret_cast<float*>(smemraw);
#pragma unroll
        for (int mt = 0; mt < 4; mt++)
#pragma unroll
            for (int nt = 0; nt < 4; nt++) {
                int r0 = wm * 64 + mt * 16 + (lane >> 2);
                int c0 = wn * 32 + nt * 8 + (lane & 3) * 2;
#pragma unroll
                for (int half = 0; half < 2; half++) {
                    int r = r0 + half * 8;
                    SM[r * EP2_LD + c0]     = acc[mt][nt][half * 2];
                    SM[r * EP2_LD + c0 + 1] = acc[mt][nt][half * 2 + 1];
                }
            }
        __syncthreads();
        const int fcol0 = blockIdx.x * 64;
#pragma unroll
        for (int j = 0; j < 4; j++) {
            int idx8 = (tid + j * 256) * 8;   // 128 rows x 64 f-cols
            int row = idx8 >> 6, c = idx8 & 63;
            const float* p1 = SM + row * EP2_LD + c;
            const float* p2 = p1 + 64;
            float v[8];
#pragma unroll
            for (int e = 0; e < 8; e++) {
                float a = p1[e];
                v[e] = (a / (1.f + expf(-a))) * p2[e];
            }
            size_t go = (size_t)(bm + row) * HIDP + fcol0 + c;
            split8_store(v, Ghi + go, Glo + go);
        }
    } else {
#pragma unroll
        for (int mt = 0; mt < 4; mt++)
#pragma unroll
            for (int nt = 0; nt < 4; nt++) {
                int r0 = bm + wm * 64 + mt * 16 + (lane >> 2);
                int c0 = bn + wn * 32 + nt * 8 + (lane & 3) * 2;
#pragma unroll
                for (int half = 0; half < 2; half++) {
                    int r = r0 + half * 8;
                    float2 v = make_float2(acc[mt][nt][half * 2], acc[mt][nt][half * 2 + 1]);
                    if (Res) {
                        float2 rv = *reinterpret_cast<const float2*>(&Res[(size_t)r * N + c0]);
                        v.x += rv.x; v.y += rv.y;
                    }
                    *reinterpret_cast<float2*>(&C[(size_t)r * N + c0]) = v;
                }
            }
    }
}

// ================= chunkwise retention =================
#define RC_SMEM ((128*68 + 64*136)*4)

__global__ __launch_bounds__(256, 1)
void ret_contrib(const float* __restrict__ K, const float* __restrict__ V,
                 float* __restrict__ CS)
{
    extern __shared__ float smc[];
    float* KsT = smc;
    float* Vs  = KsT + 128 * 68;

    const int tid  = threadIdx.x;
    const int lane = tid & 31;
    const int warp = tid >> 5;
    const int gq = lane >> 2;
    const int tg = lane & 3;
    const int wm = warp >> 2;
    const int wn = warp & 3;
    const int chunk = blockIdx.x;
    const int bh = blockIdx.y;
    const int b = bh >> 4, h = bh & 15;
    const int kb = chunk * 64;

    const float gamma = 1.f - exp2f(-5.f - (float)h);
    const float lg = log2f(gamma);
    const size_t rowbase = (size_t)(b * SL) * QST + (size_t)h * DH;

#pragma unroll
    for (int it = 0; it < 32; it++) {
        int idx = tid + it * 256;
        int t = idx >> 7, d = idx & 127;
        size_t gidx = rowbase + (size_t)(kb + t) * QST + d;
        float w = 0.08838834764831845f * exp2f((float)(63 - t) * lg);
        KsT[d * 68 + t] = __uint_as_float(f2tf(w * K[gidx]));
        Vs[t * 136 + d] = __uint_as_float(f2tf(V[gidx]));
    }
    __syncthreads();

    float acc[4][4][4];
#pragma unroll
    for (int a = 0; a < 4; a++)
#pragma unroll
        for (int bq = 0; bq < 4; bq++)
#pragma unroll
            for (int c = 0; c < 4; c++) acc[a][bq][c] = 0.f;

#pragma unroll
    for (int ks = 0; ks < 8; ks++) {
        const int kkk = ks * 8;
        unsigned af[4][4], bf[4][2];
#pragma unroll
        for (int mt = 0; mt < 4; mt++) {
            int m = wm * 64 + mt * 16 + gq;
            af[mt][0] = __float_as_uint(KsT[m * 68 + kkk + tg]);
            af[mt][1] = __float_as_uint(KsT[(m + 8) * 68 + kkk + tg]);
            af[mt][2] = __float_as_uint(KsT[m * 68 + kkk + tg + 4]);
            af[mt][3] = __float_as_uint(KsT[(m + 8) * 68 + kkk + tg + 4]);
        }
#pragma unroll
        for (int nt = 0; nt < 4; nt++) {
            int n = wn * 32 + nt * 8 + gq;
            bf[nt][0] = __float_as_uint(Vs[(kkk + tg) * 136 + n]);
            bf[nt][1] = __float_as_uint(Vs[(kkk + tg + 4) * 136 + n]);
        }
#pragma unroll
        for (int mt = 0; mt < 4; mt++)
#pragma unroll
            for (int nt = 0; nt < 4; nt++)
                mma8(acc[mt][nt], af[mt], bf[nt]);
    }

    float* outp = CS + ((size_t)bh * NCH + chunk) * (DH * DH);
#pragma unroll
    for (int mt = 0; mt < 4; mt++)
#pragma unroll
        for (int nt = 0; nt < 4; nt++) {
            int r0 = wm * 64 + mt * 16 + gq;
            int c0 = wn * 32 + nt * 8 + tg * 2;
#pragma unroll
            for (int e = 0; e < 4; e++) {
                int r = r0 + (e >> 1) * 8;
                int c = c0 + (e & 1);
                outp[r * DH + c] = acc[mt][nt][e];
            }
        }
}

__global__ __launch_bounds__(512)
void ret_scan(float* __restrict__ CS)
{
    const int bh = blockIdx.x;
    const int h = bh & 15;
    const float gamma = 1.f - exp2f(-5.f - (float)h);
    const float dec = exp2f(64.f * log2f(gamma));
    float* base = CS + (size_t)bh * NCH * (DH * DH);
    const int tid = threadIdx.x;

    float s[32];
#pragma unroll
    for (int j = 0; j < 32; j++) s[j] = 0.f;
    for (int i = 0; i < NCH; i++) {
        float* p = base + (size_t)i * (DH * DH);
#pragma unroll
        for (int j = 0; j < 32; j++) {
            int e = tid + j * 512;
            float c = p[e];
            p[e] = s[j];
            s[j] = s[j] * dec + c;
        }
    }
}

// ret_out with fused per-head GroupNorm + silu gate epilogue -> a_hi/a_lo (bf16)
#define RO_SMEM ((64*132*2 + 64*136 + 64*68 + 128*136 + 128 + 64)*4)

__global__ __launch_bounds__(256, 1)
void ret_out(const float* __restrict__ Q, const float* __restrict__ Kt,
             const float* __restrict__ V, const float* __restrict__ CS,
             const float* __restrict__ QKVG,
             bf16* __restrict__ Ahi, bf16* __restrict__ Alo)
{
    extern __shared__ float smr[];
    float* Qs  = smr;                // [64][132] (reused as output stage)
    float* Ks  = Qs + 64 * 132;
    float* Vs  = Ks + 64 * 132;
    float* Ss  = Vs + 64 * 136;
    float* Sts = Ss + 64 * 68;
    float* dp  = Sts + 128 * 136;
    float* dp2 = dp + 128;

    const int tid  = threadIdx.x;
    const int lane = tid & 31;
    const int warp = tid >> 5;
    const int gq = lane >> 2;
    const int tg = lane & 3;
    const int wm = warp >> 2;
    const int wn = warp & 3;
    const int chunk = blockIdx.x;
    const int bh = blockIdx.y;
    const int b = bh >> 4, h = bh & 15;
    const int qb = chunk * 64;

    const float gamma = 1.f - exp2f(-5.f - (float)h);
    const float lg = log2f(gamma);
    const size_t rowbase = (size_t)(b * SL) * QST + (size_t)h * DH;
    const float* stp = CS + ((size_t)bh * NCH + chunk) * (DH * DH);

#pragma unroll
    for (int it = 0; it < 32; it++) {
        int idx = tid + it * 256;
        int r = idx >> 7, d = idx & 127;
        size_t gidx = rowbase + (size_t)(qb + r) * QST + d;
        Qs[r * 132 + d] = __uint_as_float(f2tf(Q[gidx]));
        Ks[r * 132 + d] = __uint_as_float(f2tf(Kt[gidx]));
        Vs[r * 136 + d] = __uint_as_float(f2tf(V[gidx]));
    }
#pragma unroll
    for (int it = 0; it < 64; it++) {
        int idx = tid + it * 256;
        int r = idx >> 7, d = idx & 127;
        Sts[r * 136 + d] = __uint_as_float(f2tf(stp[idx]));
    }
    if (tid < 128) {
        int e = tid - 63;
        dp[tid] = (e < 0) ? 0.f : 0.08838834764831845f * exp2f((float)e * lg);
    }
    if (tid < 64) dp2[tid] = exp2f((float)(tid + 1) * lg);
    __syncthreads();

    float acco[2][4][4];
#pragma unroll
    for (int a = 0; a < 2; a++)
#pragma unroll
        for (int bq = 0; bq < 4; bq++)
#pragma unroll
            for (int c = 0; c < 4; c++) acco[a][bq][c] = 0.f;

#pragma unroll
    for (int ks = 0; ks < 16; ks++) {
        const int kkk = ks * 8;
        unsigned af[2][4], bf[4][2];
#pragma unroll
        for (int mt = 0; mt < 2; mt++) {
            int m = wm * 32 + mt * 16 + gq;
            af[mt][0] = __float_as_uint(Qs[m * 132 + kkk + tg]);
            af[mt][1] = __float_as_uint(Qs[(m + 8) * 132 + kkk + tg]);
            af[mt][2] = __float_as_uint(Qs[m * 132 + kkk + tg + 4]);
            af[mt][3] = __float_as_uint(Qs[(m + 8) * 132 + kkk + tg + 4]);
        }
#pragma unroll
        for (int nt = 0; nt < 4; nt++) {
            int n = wn * 32 + nt * 8 + gq;
            bf[nt][0] = __float_as_uint(Sts[(kkk + tg) * 136 + n]);
            bf[nt][1] = __float_as_uint(Sts[(kkk + tg + 4) * 136 + n]);
        }
#pragma unroll
        for (int mt = 0; mt < 2; mt++)
#pragma unroll
            for (int nt = 0; nt < 4; nt++)
                mma8(acco[mt][nt], af[mt], bf[nt]);
    }
#pragma unroll
    for (int mt = 0; mt < 2; mt++) {
        int r0 = wm * 32 + mt * 16 + gq;
        float sc0 = dp2[r0], sc1 = dp2[r0 + 8];
#pragma unroll
        for (int nt = 0; nt < 4; nt++) {
            acco[mt][nt][0] *= sc0; acco[mt][nt][1] *= sc0;
            acco[mt][nt][2] *= sc1; acco[mt][nt][3] *= sc1;
        }
    }

    float accs[2][2][4];
#pragma unroll
    for (int a = 0; a < 2; a++)
#pragma unroll
        for (int bq = 0; bq < 2; bq++)
#pragma unroll
            for (int c = 0; c < 4; c++) accs[a][bq][c] = 0.f;
#pragma unroll
    for (int ks = 0; ks < 16; ks++) {
        const int kkk = ks * 8;
        unsigned af[2][4], bf[2][2];
#pragma unroll
        for (int mt = 0; mt < 2; mt++) {
            int m = wm * 32 + mt * 16 + gq;
            af[mt][0] = __float_as_uint(Qs[m * 132 + kkk + tg]);
            af[mt][1] = __float_as_uint(Qs[(m + 8) * 132 + kkk + tg]);
            af[mt][2] = __float_as_uint(Qs[m * 132 + kkk + tg + 4]);
            af[mt][3] = __float_as_uint(Qs[(m + 8) * 132 + kkk + tg + 4]);
        }
#pragma unroll
        for (int nt = 0; nt < 2; nt++) {
            int n = wn * 16 + nt * 8 + gq;
            bf[nt][0] = __float_as_uint(Ks[n * 132 + kkk + tg]);
            bf[nt][1] = __float_as_uint(Ks[n * 132 + kkk + tg + 4]);
        }
#pragma unroll
        for (int mt = 0; mt < 2; mt++)
#pragma unroll
            for (int nt = 0; nt < 2; nt++)
                mma8(accs[mt][nt], af[mt], bf[nt]);
    }
#pragma unroll
    for (int mt = 0; mt < 2; mt++)
#pragma unroll
        for (int nt = 0; nt < 2; nt++) {
            int sr0 = wm * 32 + mt * 16 + gq;
            int tc0 = wn * 16 + nt * 8 + tg * 2;
#pragma unroll
            for (int e = 0; e < 4; e++) {
                int sr = sr0 + (e >> 1) * 8;
                int tc = tc0 + (e & 1);
                float coeff = dp[sr - tc + 63];
                Ss[sr * 68 + tc] = __uint_as_float(f2tf(accs[mt][nt][e] * coeff));
            }
        }
    __syncthreads();

#pragma unroll
    for (int ks = 0; ks < 8; ks++) {
        const int kkk = ks * 8;
        unsigned af[2][4], bf[4][2];
#pragma unroll
        for (int mt = 0; mt < 2; mt++) {
            int m = wm * 32 + mt * 16 + gq;
            af[mt][0] = __float_as_uint(Ss[m * 68 + kkk + tg]);
            af[mt][1] = __float_as_uint(Ss[(m + 8) * 68 + kkk + tg]);
            af[mt][2] = __float_as_uint(Ss[m * 68 + kkk + tg + 4]);
            af[mt][3] = __float_as_uint(Ss[(m + 8) * 68 + kkk + tg + 4]);
        }
#pragma unroll
        for (int nt = 0; nt < 4; nt++) {
            int n = wn * 32 + nt * 8 + gq;
            bf[nt][0] = __float_as_uint(Vs[(kkk + tg) * 136 + n]);
            bf[nt][1] = __float_as_uint(Vs[(kkk + tg + 4) * 136 + n]);
        }
#pragma unroll
        for (int mt = 0; mt < 2; mt++)
#pragma unroll
            for (int nt = 0; nt < 4; nt++)
                mma8(acco[mt][nt], af[mt], bf[nt]);
    }

    // ---- fused epilogue: stage to smem, per-row groupnorm + silu gate -> bf16 hi/lo
    __syncthreads();   // all warps done reading Qs (OS aliases Qs)
    float* OS = Qs;    // [64][132]
#pragma unroll
    for (int mt = 0; mt < 2; mt++)
#pragma unroll
        for (int nt = 0; nt < 4; nt++) {
            int r0 = wm * 32 + mt * 16 + gq;
            int c0 = wn * 32 + nt * 8 + tg * 2;
#pragma unroll
            for (int e = 0; e < 4; e++) {
                int r = r0 + (e >> 1) * 8;
                int c = c0 + (e & 1);
                OS[r * 132 + c] = acco[mt][nt][e];
            }
        }
    __syncthreads();

#pragma unroll
    for (int i = 0; i < 8; i++) {
        int row = warp + i * 8;       // local row 0..63, one warp per row
        float4 v = *reinterpret_cast<const float4*>(OS + row * 132 + lane * 4);
        float s  = v.x + v.y + v.z + v.w;
        float ss = v.x*v.x + v.y*v.y + v.z*v.z + v.w*v.w;
#pragma unroll
        for (int o = 16; o > 0; o >>= 1) {
            s  += __shfl_xor_sync(0xFFFFFFFFu, s,  o);
            ss += __shfl_xor_sync(0xFFFFFFFFu, ss, o);
        }
        const float mean = s * (1.f / DH);
        const float var  = ss * (1.f / DH) - mean * mean;
        const float rstd = rsqrtf(var + 1e-5f);
        const int grow = b * SL + qb + row;
        float4 gv = *reinterpret_cast<const float4*>(
            QKVG + (size_t)grow * QST + 6144 + h * DH + lane * 4);
        float outv[4];
        outv[0] = (gv.x / (1.f + expf(-gv.x))) * ((v.x - mean) * rstd);
        outv[1] = (gv.y / (1.f + expf(-gv.y))) * ((v.y - mean) * rstd);
        outv[2] = (gv.z / (1.f + expf(-gv.z))) * ((v.z - mean) * rstd);
        outv[3] = (gv.w / (1.f + expf(-gv.w))) * ((v.w - mean) * rstd);
        size_t ab = (size_t)grow * DM + h * DH + lane * 4;
        split4_store(outv, Ahi + ab, Alo + ab);
    }
}

// ---------------- launch ----------------
extern "C" void kernel_launch(void* const* d_in, const int* in_sizes, int n_in,
                              void* d_out, int out_size)
{
    const float* x   = (const float*)d_in[0];
    const float* n1w = (const float*)d_in[1];
    const float* n1b = (const float*)d_in[2];
    const float* wq  = (const float*)d_in[3];
    const float* wk  = (const float*)d_in[4];
    const float* wv  = (const float*)d_in[5];
    const float* wg  = (const float*)d_in[6];
    const float* wo  = (const float*)d_in[7];
    const float* n2w = (const float*)d_in[8];
    const float* n2b = (const float*)d_in[9];
    const float* w1  = (const float*)d_in[10];
    const float* w2  = (const float*)d_in[11];
    const float* w3  = (const float*)d_in[12];
    float* out = (float*)d_out;

    float *qkvg, *x1, *cs;
    bf16 *h_hi, *h_lo, *h2_hi, *h2_lo, *a_hi, *a_lo, *fg_hi, *fg_lo;
    bf16 *wp_hi, *wp_lo, *wo_hi, *wo_lo, *w12_hi, *w12_lo, *w3_hi, *w3_lo;

    cudaGetSymbolAddress((void**)&qkvg, g_qkvg);
    cudaGetSymbolAddress((void**)&x1,   g_x1);
    cudaGetSymbolAddress((void**)&cs,   g_st);
    cudaGetSymbolAddress((void**)&h_hi,  g_h_hi);
    cudaGetSymbolAddress((void**)&h_lo,  g_h_lo);
    cudaGetSymbolAddress((void**)&h2_hi, g_h2_hi);
    cudaGetSymbolAddress((void**)&h2_lo, g_h2_lo);
    cudaGetSymbolAddress((void**)&a_hi,  g_a_hi);
    cudaGetSymbolAddress((void**)&a_lo,  g_a_lo);
    cudaGetSymbolAddress((void**)&fg_hi, g_fg_hi);
    cudaGetSymbolAddress((void**)&fg_lo, g_fg_lo);
    cudaGetSymbolAddress((void**)&wp_hi,  g_wqkvg_hi); cudaGetSymbolAddress((void**)&wp_lo,  g_wqkvg_lo);
    cudaGetSymbolAddress((void**)&wo_hi,  g_wo_hi);    cudaGetSymbolAddress((void**)&wo_lo,  g_wo_lo);
    cudaGetSymbolAddress((void**)&w12_hi, g_w12_hi);   cudaGetSymbolAddress((void**)&w12_lo, g_w12_lo);
    cudaGetSymbolAddress((void**)&w3_hi,  g_w3_hi);    cudaGetSymbolAddress((void**)&w3_lo,  g_w3_lo);

    cudaFuncSetAttribute((const void*)gemm2_bf16x3,
                         cudaFuncAttributeMaxDynamicSharedMemorySize, GEMM2_SMEM);
    cudaFuncSetAttribute((const void*)ret_contrib,
                         cudaFuncAttributeMaxDynamicSharedMemorySize, RC_SMEM);
    cudaFuncSetAttribute((const void*)ret_out,
                         cudaFuncAttributeMaxDynamicSharedMemorySize, RO_SMEM);

    // positions 1-3
    conv_qkvg<<<4096, 256>>>(wq, wk, wv, wg, wp_hi, wp_lo);
    conv_wo<<<2048, 256>>>(wo, wo_hi, wo_lo);
    ln_kernel<<<BSROWS, 256>>>(x, n1w, n1b, h_hi, h_lo);

    // position 4: qkvg GEMM (ncu capture target)
    gemm2_bf16x3<<<dim3(QST / 128, BSROWS / 128), 256, GEMM2_SMEM>>>(
        h_hi, h_lo, wp_hi, wp_lo, nullptr, qkvg, nullptr, nullptr, QST, DM);

    conv_w12<<<4096, 256>>>(w1, w2, w12_hi, w12_lo);
    conv_w3<<<2048, 256>>>(w3, w3_hi, w3_lo);

    ret_contrib<<<dim3(NCH, NB * NH), 256, RC_SMEM>>>(qkvg + 2048, qkvg + 4096, cs);
    ret_scan<<<NB * NH, 512>>>(cs);
    // fused retention-out + groupnorm + silu gate -> a_hi/a_lo
    ret_out<<<dim3(NCH, NB * NH), 256, RO_SMEM>>>(
        qkvg, qkvg + 2048, qkvg + 4096, cs, qkvg, a_hi, a_lo);

    gemm2_bf16x3<<<dim3(DM / 128, BSROWS / 128), 256, GEMM2_SMEM>>>(
        a_hi, a_lo, wo_hi, wo_lo, x, x1, nullptr, nullptr, DM, DM);

    ln_kernel<<<BSROWS, 256>>>(x1, n2w, n2b, h2_hi, h2_lo);

    // w12 GEMM with fused silu-gate epilogue (64-col interleave) -> fg
    gemm2_bf16x3<<<dim3(FST / 128, BSROWS / 128), 256, GEMM2_SMEM>>>(
        h2_hi, h2_lo, w12_hi, w12_lo, nullptr, nullptr, fg_hi, fg_lo, FST, DM);

    gemm2_bf16x3<<<dim3(DM / 128, BSROWS / 128), 256, GEMM2_SMEM>>>(
        fg_hi, fg_lo, w3_hi, w3_lo, x1, out, nullptr, nullptr, DM, HIDP);
}

// round 15
// speedup vs baseline: 1.0392x; 1.0065x over previous
#include <cuda_runtime.h>
#include <cuda_bf16.h>
#include <cstdint>
#include <cstddef>

#define NB 2
#define SL 2048
#define DM 2048
#define NH 16
#define DH 128
#define HIDN 5461
#define HIDP 5504
#define BSROWS (NB*SL)      // 4096
#define NCH 32
#define QST 8192            // packed qkvg row stride
#define FST 11008           // packed interleaved w1|w2 col count (64-blocks)

typedef __nv_bfloat16 bf16;

// ---------------- scratch ----------------
__device__ float g_qkvg[(size_t)BSROWS*QST];
__device__ float g_x1[(size_t)BSROWS*DM];
__device__ float g_st[(size_t)NB*NH*NCH*DH*DH];

__device__ __align__(16) bf16 g_h_hi [(size_t)BSROWS*DM];
__device__ __align__(16) bf16 g_h_lo [(size_t)BSROWS*DM];
__device__ __align__(16) bf16 g_h2_hi[(size_t)BSROWS*DM];
__device__ __align__(16) bf16 g_h2_lo[(size_t)BSROWS*DM];
__device__ __align__(16) bf16 g_a_hi [(size_t)BSROWS*DM];
__device__ __align__(16) bf16 g_a_lo [(size_t)BSROWS*DM];
__device__ __align__(16) bf16 g_fg_hi[(size_t)BSROWS*HIDP];
__device__ __align__(16) bf16 g_fg_lo[(size_t)BSROWS*HIDP];

__device__ __align__(16) bf16 g_wqkvg_hi[(size_t)DM*QST], g_wqkvg_lo[(size_t)DM*QST];
__device__ __align__(16) bf16 g_wo_hi[(size_t)DM*DM],  g_wo_lo[(size_t)DM*DM];
__device__ __align__(16) bf16 g_w12_hi[(size_t)DM*FST], g_w12_lo[(size_t)DM*FST];
__device__ __align__(16) bf16 g_w3_hi[(size_t)HIDP*DM], g_w3_lo[(size_t)HIDP*DM];

// ---------------- side-stream aux (host objects only; created at load) ------
namespace {
struct Aux {
    cudaStream_t s2;
    cudaEvent_t ev0, evA, evB;
    Aux() {
        cudaStreamCreateWithFlags(&s2, cudaStreamNonBlocking);
        cudaEventCreateWithFlags(&ev0, cudaEventDisableTiming);
        cudaEventCreateWithFlags(&evA, cudaEventDisableTiming);
        cudaEventCreateWithFlags(&evB, cudaEventDisableTiming);
    }
};
Aux g_aux;
}

// ---------------- helpers ----------------
__device__ __forceinline__ unsigned f2tf(float x) {
    unsigned r;
    asm("cvt.rna.tf32.f32 %0, %1;" : "=r"(r) : "f"(x));
    return r;
}

__device__ __forceinline__ void split_bf16(float x, bf16& hi, bf16& lo) {
    hi = __float2bfloat16(x);
    lo = __float2bfloat16(x - __bfloat162float(hi));
}

__device__ __forceinline__ void split8_store(const float* v, bf16* hip, bf16* lop) {
    bf16 hh[8], ll[8];
#pragma unroll
    for (int j = 0; j < 8; j++) split_bf16(v[j], hh[j], ll[j]);
    *reinterpret_cast<uint4*>(hip) = *reinterpret_cast<uint4*>(hh);
    *reinterpret_cast<uint4*>(lop) = *reinterpret_cast<uint4*>(ll);
}

__device__ __forceinline__ void split4_store(const float* v, bf16* hip, bf16* lop) {
    bf16 hh[4], ll[4];
#pragma unroll
    for (int j = 0; j < 4; j++) split_bf16(v[j], hh[j], ll[j]);
    *reinterpret_cast<uint2*>(hip) = *reinterpret_cast<uint2*>(hh);
    *reinterpret_cast<uint2*>(lop) = *reinterpret_cast<uint2*>(ll);
}

__device__ __forceinline__ void mma8(float* c, const unsigned* a, const unsigned* b) {
    asm volatile(
        "mma.sync.aligned.m16n8k8.row.col.f32.tf32.tf32.f32 "
        "{%0,%1,%2,%3}, {%4,%5,%6,%7}, {%8,%9}, {%0,%1,%2,%3};\n"
        : "+f"(c[0]), "+f"(c[1]), "+f"(c[2]), "+f"(c[3])
        : "r"(a[0]), "r"(a[1]), "r"(a[2]), "r"(a[3]), "r"(b[0]), "r"(b[1]));
}

__device__ __forceinline__ void mma16(float* c, const unsigned* a, const unsigned* b) {
    asm volatile(
        "mma.sync.aligned.m16n8k16.row.col.f32.bf16.bf16.f32 "
        "{%0,%1,%2,%3}, {%4,%5,%6,%7}, {%8,%9}, {%0,%1,%2,%3};\n"
        : "+f"(c[0]), "+f"(c[1]), "+f"(c[2]), "+f"(c[3])
        : "r"(a[0]), "r"(a[1]), "r"(a[2]), "r"(a[3]), "r"(b[0]), "r"(b[1]));
}

__device__ __forceinline__ void ldsm4(unsigned* r, unsigned addr) {
    asm volatile("ldmatrix.sync.aligned.m8n8.x4.shared.b16 {%0,%1,%2,%3}, [%4];\n"
        : "=r"(r[0]), "=r"(r[1]), "=r"(r[2]), "=r"(r[3]) : "r"(addr));
}
__device__ __forceinline__ void ldsm4t(unsigned* r, unsigned addr) {
    asm volatile("ldmatrix.sync.aligned.m8n8.x4.trans.shared.b16 {%0,%1,%2,%3}, [%4];\n"
        : "=r"(r[0]), "=r"(r[1]), "=r"(r[2]), "=r"(r[3]) : "r"(addr));
}
__device__ __forceinline__ void cpa16(unsigned dst, const void* src) {
    asm volatile("cp.async.cg.shared.global [%0], [%1], 16;\n" :: "r"(dst), "l"(src));
}

// ---------------- weight packers ----------------
__global__ __launch_bounds__(256)
void conv_qkvg(const float* __restrict__ wq, const float* __restrict__ wk,
               const float* __restrict__ wv, const float* __restrict__ wg,
               bf16* __restrict__ hi, bf16* __restrict__ lo)
{
    const size_t n8 = (size_t)DM * QST / 8;
    size_t i = (size_t)blockIdx.x * 256 + threadIdx.x;
    const size_t st = (size_t)gridDim.x * 256;
    for (; i < n8; i += st) {
        size_t i8 = i * 8;
        size_t k = i8 >> 13;
        int c = (int)(i8 & (QST - 1));
        int proj = c >> 11, col = c & 2047;
        const float* s = (proj == 0) ? wq : (proj == 1) ? wk : (proj == 2) ? wv : wg;
        float v[8];
        *reinterpret_cast<float4*>(v)     = *reinterpret_cast<const float4*>(s + k * DM + col);
        *reinterpret_cast<float4*>(v + 4) = *reinterpret_cast<const float4*>(s + k * DM + col + 4);
        split8_store(v, hi + i8, lo + i8);
    }
}

__global__ __launch_bounds__(256)
void conv_wo(const float* __restrict__ src, bf16* __restrict__ hi, bf16* __restrict__ lo)
{
    const size_t n8 = (size_t)DM * DM / 8;
    size_t i = (size_t)blockIdx.x * 256 + threadIdx.x;
    const size_t st = (size_t)gridDim.x * 256;
    for (; i < n8; i += st) {
        size_t i8 = i * 8;
        float v[8];
        *reinterpret_cast<float4*>(v)     = *reinterpret_cast<const float4*>(src + i8);
        *reinterpret_cast<float4*>(v + 4) = *reinterpret_cast<const float4*>(src + i8 + 4);
        split8_store(v, hi + i8, lo + i8);
    }
}

// interleaved at 64-col granularity: 64-col blocks alternate w1/w2.
__global__ __launch_bounds__(256)
void conv_w12(const float* __restrict__ w1, const float* __restrict__ w2,
              bf16* __restrict__ hi, bf16* __restrict__ lo)
{
    const size_t n8 = (size_t)DM * FST / 8;
    size_t i = (size_t)blockIdx.x * 256 + threadIdx.x;
    const size_t st = (size_t)gridDim.x * 256;
    for (; i < n8; i += st) {
        size_t i8 = i * 8;
        size_t k = i8 / FST;
        int c = (int)(i8 - k * FST);
        int blk = c >> 6;
        int fcol = (blk >> 1) * 64 + (c & 63);
        const float* w = (blk & 1) ? w2 : w1;
        float v[8];
#pragma unroll
        for (int j = 0; j < 8; j++) {
            int col = fcol + j;
            v[j] = (col < HIDN) ? w[k * HIDN + col] : 0.f;
        }
        split8_store(v, hi + i8, lo + i8);
    }
}

__global__ __launch_bounds__(256)
void conv_w3(const float* __restrict__ w3, bf16* __restrict__ hi, bf16* __restrict__ lo)
{
    const size_t n8 = (size_t)HIDP * DM / 8;
    size_t i = (size_t)blockIdx.x * 256 + threadIdx.x;
    const size_t st = (size_t)gridDim.x * 256;
    for (; i < n8; i += st) {
        size_t i8 = i * 8;
        int r = (int)(i8 >> 11);
        float v[8];
        if (r < HIDN) {
            *reinterpret_cast<float4*>(v)     = *reinterpret_cast<const float4*>(w3 + i8);
            *reinterpret_cast<float4*>(v + 4) = *reinterpret_cast<const float4*>(w3 + i8 + 4);
        } else {
#pragma unroll
            for (int j = 0; j < 8; j++) v[j] = 0.f;
        }
        split8_store(v, hi + i8, lo + i8);
    }
}

// ---------------- LayerNorm -> bf16 hi/lo ----------------
__global__ __launch_bounds__(256)
void ln_kernel(const float* __restrict__ x, const float* __restrict__ w,
               const float* __restrict__ b, bf16* __restrict__ ohi,
               bf16* __restrict__ olo)
{
    __shared__ float red[16];
    const int row = blockIdx.x;
    const float* xr = x + (size_t)row * DM;
    float vals[8];
    float s = 0.f, ss = 0.f;
#pragma unroll
    for (int j = 0; j < 8; j++) {
        float v = xr[threadIdx.x + j * 256];
        vals[j] = v; s += v; ss += v * v;
    }
#pragma unroll
    for (int o = 16; o > 0; o >>= 1) {
        s  += __shfl_xor_sync(0xFFFFFFFFu, s,  o);
        ss += __shfl_xor_sync(0xFFFFFFFFu, ss, o);
    }
    const int warp = threadIdx.x >> 5, lane = threadIdx.x & 31;
    if (lane == 0) { red[warp] = s; red[8 + warp] = ss; }
    __syncthreads();
    s = 0.f; ss = 0.f;
#pragma unroll
    for (int k = 0; k < 8; k++) { s += red[k]; ss += red[8 + k]; }
    const float mean = s * (1.f / DM);
    const float var  = ss * (1.f / DM) - mean * mean;
    const float rstd = rsqrtf(var + 1e-5f);
#pragma unroll
    for (int j = 0; j < 8; j++) {
        int col = threadIdx.x + j * 256;
        float o = (vals[j] - mean) * rstd * w[col] + b[col];
        split_bf16(o, ohi[(size_t)row * DM + col], olo[(size_t)row * DM + col]);
    }
}

// ---------------- bf16x3 GEMM: CTA 128x128, 3-stage, 2 CTAs/SM ----------------
#define STG2_B 37888u
#define OFF2_AL 10240u
#define OFF2_BH 20480u
#define OFF2_BL 29184u
#define NSTG2 3u
#define GEMM2_SMEM (NSTG2*STG2_B)   // 113664 -> 2 CTAs = 227328 <= 228KB
#define EP2_LD 132                  // gated epilogue smem row stride (floats)

__global__ __launch_bounds__(256, 2)
void gemm2_bf16x3(const bf16* __restrict__ Ahi, const bf16* __restrict__ Alo,
                  const bf16* __restrict__ Bhi, const bf16* __restrict__ Blo,
                  const float* __restrict__ Res, float* __restrict__ C,
                  bf16* __restrict__ Ghi, bf16* __restrict__ Glo,
                  int N, int K)
{
    extern __shared__ __align__(16) char smemraw[];
    const unsigned s0 = (unsigned)__cvta_generic_to_shared(smemraw);

    const int tid  = threadIdx.x;
    const int lane = tid & 31;
    const int warp = tid >> 5;
    const int wm = warp >> 2;     // 0..1 : 64 rows
    const int wn = warp & 3;      // 0..3 : 32 cols
    const int bm = blockIdx.y * 128;
    const int bn = blockIdx.x * 128;

    // pointer-increment prefetch state (computed once)
    const int arow = tid >> 2, achn = tid & 3;
    const int brow = tid >> 4, bchn = tid & 15;
    const bf16* pAh = Ahi + (size_t)(bm + arow) * K + achn * 8;
    const bf16* pAl = Alo + (size_t)(bm + arow) * K + achn * 8;
    const bf16* pBh = Bhi + (size_t)brow * N + bn + bchn * 8;
    const bf16* pBl = Blo + (size_t)brow * N + bn + bchn * 8;
    const size_t aStep = 64 * (size_t)K;    // second A chunk (row +64)
    const size_t bStep = 16 * (size_t)N;    // second B chunk (row +16)
    const size_t bAdv  = 32 * (size_t)N;    // per-stage B advance
    const unsigned soA = (unsigned)(arow * 80 + achn * 16);
    const unsigned soB = (unsigned)(brow * 272 + bchn * 16);

#define G2_PREFETCH(stg)                                           \
    do {                                                           \
        unsigned _s = (stg);                                       \
        cpa16(_s + soA,              pAh);                         \
        cpa16(_s + soA + 5120u,      pAh + aStep);                 \
        cpa16(_s + OFF2_AL + soA,         pAl);                    \
        cpa16(_s + OFF2_AL + soA + 5120u, pAl + aStep);            \
        cpa16(_s + OFF2_BH + soB,         pBh);                    \
        cpa16(_s + OFF2_BH + soB + 4352u, pBh + bStep);            \
        cpa16(_s + OFF2_BL + soB,         pBl);                    \
        cpa16(_s + OFF2_BL + soB + 4352u, pBl + bStep);            \
        asm volatile("cp.async.commit_group;\n" ::: "memory");     \
        pAh += 32; pAl += 32; pBh += bAdv; pBl += bAdv;            \
    } while (0)

    const unsigned laneA = (unsigned)(((lane & 7) + ((lane >> 3) & 1) * 8) * 80 + (lane >> 4) * 16);
    const unsigned laneB = (unsigned)(((lane & 7) + ((lane >> 3) & 1) * 8) * 272 + (lane >> 4) * 16);

    float acc[4][4][4];
#pragma unroll
    for (int a = 0; a < 4; a++)
#pragma unroll
        for (int b = 0; b < 4; b++)
#pragma unroll
            for (int c = 0; c < 4; c++) acc[a][b][c] = 0.f;

    const int nk = K >> 5;
    G2_PREFETCH(s0);
    G2_PREFETCH(s0 + STG2_B);

    unsigned stage = 0;
    for (int t = 0; t < nk; t++) {
        if (t + 1 < nk) asm volatile("cp.async.wait_group 1;\n" ::: "memory");
        else            asm volatile("cp.async.wait_group 0;\n" ::: "memory");
        __syncthreads();

        if (t + 2 < nk) {
            unsigned nst = stage + 2u * STG2_B;
            if (nst >= NSTG2 * STG2_B) nst -= NSTG2 * STG2_B;
            G2_PREFETCH(s0 + nst);
        }

        const unsigned st = s0 + stage;
        const unsigned aBase = st + (unsigned)(wm * 64 * 80) + laneA;
        const unsigned bBase = st + OFF2_BH + (unsigned)(wn * 32 * 2) + laneB;

#pragma unroll
        for (int ks = 0; ks < 2; ks++) {
            unsigned ah[4][4], al[4][4];
#pragma unroll
            for (int mt = 0; mt < 4; mt++) {
                unsigned ad = aBase + (unsigned)(mt * 16 * 80 + ks * 32);
                ldsm4(ah[mt], ad);
                ldsm4(al[mt], ad + OFF2_AL);
            }
#pragma unroll
            for (int p = 0; p < 2; p++) {
                unsigned bh[4], bl[4];
                unsigned bd = bBase + (unsigned)(ks * 16 * 272 + p * 32);
                ldsm4t(bh, bd);
                ldsm4t(bl, bd + (OFF2_BL - OFF2_BH));
#pragma unroll
                for (int mt = 0; mt < 4; mt++) {
                    mma16(acc[mt][2*p],   ah[mt], bh);
                    mma16(acc[mt][2*p],   ah[mt], bl);
                    mma16(acc[mt][2*p],   al[mt], bh);
                    mma16(acc[mt][2*p+1], ah[mt], bh + 2);
                    mma16(acc[mt][2*p+1], ah[mt], bl + 2);
                    mma16(acc[mt][2*p+1], al[mt], bh + 2);
                }
            }
        }
        stage += STG2_B;
        if (stage >= NSTG2 * STG2_B) stage = 0;
    }
#undef G2_PREFETCH

    if (Ghi) {
        // gated epilogue: tile cols [0,64)=f1, [64,128)=f2 (same f-col range)
        __syncthreads();
        float* SM = reinterpret_cast<float*>(smemraw);
#pragma unroll
        for (int mt = 0; mt < 4; mt++)
#pragma unroll
            for (int nt = 0; nt < 4; nt++) {
                int r0 = wm * 64 + mt * 16 + (lane >> 2);
                int c0 = wn * 32 + nt * 8 + (lane & 3) * 2;
#pragma unroll
                for (int half = 0; half < 2; half++) {
                    int r = r0 + half * 8;
                    SM[r * EP2_LD + c0]     = acc[mt][nt][half * 2];
                    SM[r * EP2_LD + c0 + 1] = acc[mt][nt][half * 2 + 1];
                }
            }
        __syncthreads();
        const int fcol0 = blockIdx.x * 64;
#pragma unroll
        for (int j = 0; j < 4; j++) {
            int idx8 = (tid + j * 256) * 8;   // 128 rows x 64 f-cols
            int row = idx8 >> 6, c = idx8 & 63;
            const float* p1 = SM + row * EP2_LD + c;
            const float* p2 = p1 + 64;
            float v[8];
#pragma unroll
            for (int e = 0; e < 8; e++) {
                float a = p1[e];
                v[e] = (a / (1.f + expf(-a))) * p2[e];
            }
            size_t go = (size_t)(bm + row) * HIDP + fcol0 + c;
            split8_store(v, Ghi + go, Glo + go);
        }
    } else {
#pragma unroll
        for (int mt = 0; mt < 4; mt++)
#pragma unroll
            for (int nt = 0; nt < 4; nt++) {
                int r0 = bm + wm * 64 + mt * 16 + (lane >> 2);
                int c0 = bn + wn * 32 + nt * 8 + (lane & 3) * 2;
#pragma unroll
                for (int half = 0; half < 2; half++) {
                    int r = r0 + half * 8;
                    float2 v = make_float2(acc[mt][nt][half * 2], acc[mt][nt][half * 2 + 1]);
                    if (Res) {
                        float2 rv = *reinterpret_cast<const float2*>(&Res[(size_t)r * N + c0]);
                        v.x += rv.x; v.y += rv.y;
                    }
                    *reinterpret_cast<float2*>(&C[(size_t)r * N + c0]) = v;
                }
            }
    }
}

// ================= chunkwise retention =================
#define RC_SMEM ((128*68 + 64*136)*4)

__global__ __launch_bounds__(256, 1)
void ret_contrib(const float* __restrict__ K, const float* __restrict__ V,
                 float* __restrict__ CS)
{
    extern __shared__ float smc[];
    float* KsT = smc;
    float* Vs  = KsT + 128 * 68;

    const int tid  = threadIdx.x;
    const int lane = tid & 31;
    const int warp = tid >> 5;
    const int gq = lane >> 2;
    const int tg = lane & 3;
    const int wm = warp >> 2;
    const int wn = warp & 3;
    const int chunk = blockIdx.x;
    const int bh = blockIdx.y;
    const int b = bh >> 4, h = bh & 15;
    const int kb = chunk * 64;

    const float gamma = 1.f - exp2f(-5.f - (float)h);
    const float lg = log2f(gamma);
    const size_t rowbase = (size_t)(b * SL) * QST + (size_t)h * DH;

#pragma unroll
    for (int it = 0; it < 32; it++) {
        int idx = tid + it * 256;
        int t = idx >> 7, d = idx & 127;
        size_t gidx = rowbase + (size_t)(kb + t) * QST + d;
        float w = 0.08838834764831845f * exp2f((float)(63 - t) * lg);
        KsT[d * 68 + t] = __uint_as_float(f2tf(w * K[gidx]));
        Vs[t * 136 + d] = __uint_as_float(f2tf(V[gidx]));
    }
    __syncthreads();

    float acc[4][4][4];
#pragma unroll
    for (int a = 0; a < 4; a++)
#pragma unroll
        for (int bq = 0; bq < 4; bq++)
#pragma unroll
            for (int c = 0; c < 4; c++) acc[a][bq][c] = 0.f;

#pragma unroll
    for (int ks = 0; ks < 8; ks++) {
        const int kkk = ks * 8;
        unsigned af[4][4], bf[4][2];
#pragma unroll
        for (int mt = 0; mt < 4; mt++) {
            int m = wm * 64 + mt * 16 + gq;
            af[mt][0] = __float_as_uint(KsT[m * 68 + kkk + tg]);
            af[mt][1] = __float_as_uint(KsT[(m + 8) * 68 + kkk + tg]);
            af[mt][2] = __float_as_uint(KsT[m * 68 + kkk + tg + 4]);
            af[mt][3] = __float_as_uint(KsT[(m + 8) * 68 + kkk + tg + 4]);
        }
#pragma unroll
        for (int nt = 0; nt < 4; nt++) {
            int n = wn * 32 + nt * 8 + gq;
            bf[nt][0] = __float_as_uint(Vs[(kkk + tg) * 136 + n]);
            bf[nt][1] = __float_as_uint(Vs[(kkk + tg + 4) * 136 + n]);
        }
#pragma unroll
        for (int mt = 0; mt < 4; mt++)
#pragma unroll
            for (int nt = 0; nt < 4; nt++)
                mma8(acc[mt][nt], af[mt], bf[nt]);
    }

    float* outp = CS + ((size_t)bh * NCH + chunk) * (DH * DH);
#pragma unroll
    for (int mt = 0; mt < 4; mt++)
#pragma unroll
        for (int nt = 0; nt < 4; nt++) {
            int r0 = wm * 64 + mt * 16 + gq;
            int c0 = wn * 32 + nt * 8 + tg * 2;
#pragma unroll
            for (int e = 0; e < 4; e++) {
                int r = r0 + (e >> 1) * 8;
                int c = c0 + (e & 1);
                outp[r * DH + c] = acc[mt][nt][e];
            }
        }
}

__global__ __launch_bounds__(512)
void ret_scan(float* __restrict__ CS)
{
    const int bh = blockIdx.x;
    const int h = bh & 15;
    const float gamma = 1.f - exp2f(-5.f - (float)h);
    const float dec = exp2f(64.f * log2f(gamma));
    float* base = CS + (size_t)bh * NCH * (DH * DH);
    const int tid = threadIdx.x;

    float s[32];
#pragma unroll
    for (int j = 0; j < 32; j++) s[j] = 0.f;
    for (int i = 0; i < NCH; i++) {
        float* p = base + (size_t)i * (DH * DH);
#pragma unroll
        for (int j = 0; j < 32; j++) {
            int e = tid + j * 512;
            float c = p[e];
            p[e] = s[j];
            s[j] = s[j] * dec + c;
        }
    }
}

// ret_out with fused per-head GroupNorm + silu gate epilogue -> a_hi/a_lo (bf16)
#define RO_SMEM ((64*132*2 + 64*136 + 64*68 + 128*136 + 128 + 64)*4)

__global__ __launch_bounds__(256, 1)
void ret_out(const float* __restrict__ Q, const float* __restrict__ Kt,
             const float* __restrict__ V, const float* __restrict__ CS,
             const float* __restrict__ QKVG,
             bf16* __restrict__ Ahi, bf16* __restrict__ Alo)
{
    extern __shared__ float smr[];
    float* Qs  = smr;                // [64][132] (reused as output stage)
    float* Ks  = Qs + 64 * 132;
    float* Vs  = Ks + 64 * 132;
    float* Ss  = Vs + 64 * 136;
    float* Sts = Ss + 64 * 68;
    float* dp  = Sts + 128 * 136;
    float* dp2 = dp + 128;

    const int tid  = threadIdx.x;
    const int lane = tid & 31;
    const int warp = tid >> 5;
    const int gq = lane >> 2;
    const int tg = lane & 3;
    const int wm = warp >> 2;
    const int wn = warp & 3;
    const int chunk = blockIdx.x;
    const int bh = blockIdx.y;
    const int b = bh >> 4, h = bh & 15;
    const int qb = chunk * 64;

    const float gamma = 1.f - exp2f(-5.f - (float)h);
    const float lg = log2f(gamma);
    const size_t rowbase = (size_t)(b * SL) * QST + (size_t)h * DH;
    const float* stp = CS + ((size_t)bh * NCH + chunk) * (DH * DH);

#pragma unroll
    for (int it = 0; it < 32; it++) {
        int idx = tid + it * 256;
        int r = idx >> 7, d = idx & 127;
        size_t gidx = rowbase + (size_t)(qb + r) * QST + d;
        Qs[r * 132 + d] = __uint_as_float(f2tf(Q[gidx]));
        Ks[r * 132 + d] = __uint_as_float(f2tf(Kt[gidx]));
        Vs[r * 136 + d] = __uint_as_float(f2tf(V[gidx]));
    }
#pragma unroll
    for (int it = 0; it < 64; it++) {
        int idx = tid + it * 256;
        int r = idx >> 7, d = idx & 127;
        Sts[r * 136 + d] = __uint_as_float(f2tf(stp[idx]));
    }
    if (tid < 128) {
        int e = tid - 63;
        dp[tid] = (e < 0) ? 0.f : 0.08838834764831845f * exp2f((float)e * lg);
    }
    if (tid < 64) dp2[tid] = exp2f((float)(tid + 1) * lg);
    __syncthreads();

    float acco[2][4][4];
#pragma unroll
    for (int a = 0; a < 2; a++)
#pragma unroll
        for (int bq = 0; bq < 4; bq++)
#pragma unroll
            for (int c = 0; c < 4; c++) acco[a][bq][c] = 0.f;

#pragma unroll
    for (int ks = 0; ks < 16; ks++) {
        const int kkk = ks * 8;
        unsigned af[2][4], bf[4][2];
#pragma unroll
        for (int mt = 0; mt < 2; mt++) {
            int m = wm * 32 + mt * 16 + gq;
            af[mt][0] = __float_as_uint(Qs[m * 132 + kkk + tg]);
            af[mt][1] = __float_as_uint(Qs[(m + 8) * 132 + kkk + tg]);
            af[mt][2] = __float_as_uint(Qs[m * 132 + kkk + tg + 4]);
            af[mt][3] = __float_as_uint(Qs[(m + 8) * 132 + kkk + tg + 4]);
        }
#pragma unroll
        for (int nt = 0; nt < 4; nt++) {
            int n = wn * 32 + nt * 8 + gq;
            bf[nt][0] = __float_as_uint(Sts[(kkk + tg) * 136 + n]);
            bf[nt][1] = __float_as_uint(Sts[(kkk + tg + 4) * 136 + n]);
        }
#pragma unroll
        for (int mt = 0; mt < 2; mt++)
#pragma unroll
            for (int nt = 0; nt < 4; nt++)
                mma8(acco[mt][nt], af[mt], bf[nt]);
    }
#pragma unroll
    for (int mt = 0; mt < 2; mt++) {
        int r0 = wm * 32 + mt * 16 + gq;
        float sc0 = dp2[r0], sc1 = dp2[r0 + 8];
#pragma unroll
        for (int nt = 0; nt < 4; nt++) {
            acco[mt][nt][0] *= sc0; acco[mt][nt][1] *= sc0;
            acco[mt][nt][2] *= sc1; acco[mt][nt][3] *= sc1;
        }
    }

    float accs[2][2][4];
#pragma unroll
    for (int a = 0; a < 2; a++)
#pragma unroll
        for (int bq = 0; bq < 2; bq++)
#pragma unroll
            for (int c = 0; c < 4; c++) accs[a][bq][c] = 0.f;
#pragma unroll
    for (int ks = 0; ks < 16; ks++) {
        const int kkk = ks * 8;
        unsigned af[2][4], bf[2][2];
#pragma unroll
        for (int mt = 0; mt < 2; mt++) {
            int m = wm * 32 + mt * 16 + gq;
            af[mt][0] = __float_as_uint(Qs[m * 132 + kkk + tg]);
            af[mt][1] = __float_as_uint(Qs[(m + 8) * 132 + kkk + tg]);
            af[mt][2] = __float_as_uint(Qs[m * 132 + kkk + tg + 4]);
            af[mt][3] = __float_as_uint(Qs[(m + 8) * 132 + kkk + tg + 4]);
        }
#pragma unroll
        for (int nt = 0; nt < 2; nt++) {
            int n = wn * 16 + nt * 8 + gq;
            bf[nt][0] = __float_as_uint(Ks[n * 132 + kkk + tg]);
            bf[nt][1] = __float_as_uint(Ks[n * 132 + kkk + tg + 4]);
        }
#pragma unroll
        for (int mt = 0; mt < 2; mt++)
#pragma unroll
            for (int nt = 0; nt < 2; nt++)
                mma8(accs[mt][nt], af[mt], bf[nt]);
    }
#pragma unroll
    for (int mt = 0; mt < 2; mt++)
#pragma unroll
        for (int nt = 0; nt < 2; nt++) {
            int sr0 = wm * 32 + mt * 16 + gq;
            int tc0 = wn * 16 + nt * 8 + tg * 2;
#pragma unroll
            for (int e = 0; e < 4; e++) {
                int sr = sr0 + (e >> 1) * 8;
                int tc = tc0 + (e & 1);
                float coeff = dp[sr - tc + 63];
                Ss[sr * 68 + tc] = __uint_as_float(f2tf(accs[mt][nt][e] * coeff));
            }
        }
    __syncthreads();

#pragma unroll
    for (int ks = 0; ks < 8; ks++) {
        const int kkk = ks * 8;
        unsigned af[2][4], bf[4][2];
#pragma unroll
        for (int mt = 0; mt < 2; mt++) {
            int m = wm * 32 + mt * 16 + gq;
            af[mt][0] = __float_as_uint(Ss[m * 68 + kkk + tg]);
            af[mt][1] = __float_as_uint(Ss[(m + 8) * 68 + kkk + tg]);
            af[mt][2] = __float_as_uint(Ss[m * 68 + kkk + tg + 4]);
            af[mt][3] = __float_as_uint(Ss[(m + 8) * 68 + kkk + tg + 4]);
        }
#pragma unroll
        for (int nt = 0; nt < 4; nt++) {
            int n = wn * 32 + nt * 8 + gq;
            bf[nt][0] = __float_as_uint(Vs[(kkk + tg) * 136 + n]);
            bf[nt][1] = __float_as_uint(Vs[(kkk + tg + 4) * 136 + n]);
        }
#pragma unroll
        for (int mt = 0; mt < 2; mt++)
#pragma unroll
            for (int nt = 0; nt < 4; nt++)
                mma8(acco[mt][nt], af[mt], bf[nt]);
    }

    // ---- fused epilogue: stage to smem, per-row groupnorm + silu gate -> bf16 hi/lo
    __syncthreads();   // all warps done reading Qs (OS aliases Qs)
    float* OS = Qs;    // [64][132]
#pragma unroll
    for (int mt = 0; mt < 2; mt++)
#pragma unroll
        for (int nt = 0; nt < 4; nt++) {
            int r0 = wm * 32 + mt * 16 + gq;
            int c0 = wn * 32 + nt * 8 + tg * 2;
#pragma unroll
            for (int e = 0; e < 4; e++) {
                int r = r0 + (e >> 1) * 8;
                int c = c0 + (e & 1);
                OS[r * 132 + c] = acco[mt][nt][e];
            }
        }
    __syncthreads();

#pragma unroll
    for (int i = 0; i < 8; i++) {
        int row = warp + i * 8;       // local row 0..63, one warp per row
        float4 v = *reinterpret_cast<const float4*>(OS + row * 132 + lane * 4);
        float s  = v.x + v.y + v.z + v.w;
        float ss = v.x*v.x + v.y*v.y + v.z*v.z + v.w*v.w;
#pragma unroll
        for (int o = 16; o > 0; o >>= 1) {
            s  += __shfl_xor_sync(0xFFFFFFFFu, s,  o);
            ss += __shfl_xor_sync(0xFFFFFFFFu, ss, o);
        }
        const float mean = s * (1.f / DH);
        const float var  = ss * (1.f / DH) - mean * mean;
        const float rstd = rsqrtf(var + 1e-5f);
        const int grow = b * SL + qb + row;
        float4 gv = *reinterpret_cast<const float4*>(
            QKVG + (size_t)grow * QST + 6144 + h * DH + lane * 4);
        float outv[4];
        outv[0] = (gv.x / (1.f + expf(-gv.x))) * ((v.x - mean) * rstd);
        outv[1] = (gv.y / (1.f + expf(-gv.y))) * ((v.y - mean) * rstd);
        outv[2] = (gv.z / (1.f + expf(-gv.z))) * ((v.z - mean) * rstd);
        outv[3] = (gv.w / (1.f + expf(-gv.w))) * ((v.w - mean) * rstd);
        size_t ab = (size_t)grow * DM + h * DH + lane * 4;
        split4_store(outv, Ahi + ab, Alo + ab);
    }
}

// ---------------- launch ----------------
extern "C" void kernel_launch(void* const* d_in, const int* in_sizes, int n_in,
                              void* d_out, int out_size)
{
    const float* x   = (const float*)d_in[0];
    const float* n1w = (const float*)d_in[1];
    const float* n1b = (const float*)d_in[2];
    const float* wq  = (const float*)d_in[3];
    const float* wk  = (const float*)d_in[4];
    const float* wv  = (const float*)d_in[5];
    const float* wg  = (const float*)d_in[6];
    const float* wo  = (const float*)d_in[7];
    const float* n2w = (const float*)d_in[8];
    const float* n2b = (const float*)d_in[9];
    const float* w1  = (const float*)d_in[10];
    const float* w2  = (const float*)d_in[11];
    const float* w3  = (const float*)d_in[12];
    float* out = (float*)d_out;

    float *qkvg, *x1, *cs;
    bf16 *h_hi, *h_lo, *h2_hi, *h2_lo, *a_hi, *a_lo, *fg_hi, *fg_lo;
    bf16 *wp_hi, *wp_lo, *wo_hi, *wo_lo, *w12_hi, *w12_lo, *w3_hi, *w3_lo;

    cudaGetSymbolAddress((void**)&qkvg, g_qkvg);
    cudaGetSymbolAddress((void**)&x1,   g_x1);
    cudaGetSymbolAddress((void**)&cs,   g_st);
    cudaGetSymbolAddress((void**)&h_hi,  g_h_hi);
    cudaGetSymbolAddress((void**)&h_lo,  g_h_lo);
    cudaGetSymbolAddress((void**)&h2_hi, g_h2_hi);
    cudaGetSymbolAddress((void**)&h2_lo, g_h2_lo);
    cudaGetSymbolAddress((void**)&a_hi,  g_a_hi);
    cudaGetSymbolAddress((void**)&a_lo,  g_a_lo);
    cudaGetSymbolAddress((void**)&fg_hi, g_fg_hi);
    cudaGetSymbolAddress((void**)&fg_lo, g_fg_lo);
    cudaGetSymbolAddress((void**)&wp_hi,  g_wqkvg_hi); cudaGetSymbolAddress((void**)&wp_lo,  g_wqkvg_lo);
    cudaGetSymbolAddress((void**)&wo_hi,  g_wo_hi);    cudaGetSymbolAddress((void**)&wo_lo,  g_wo_lo);
    cudaGetSymbolAddress((void**)&w12_hi, g_w12_hi);   cudaGetSymbolAddress((void**)&w12_lo, g_w12_lo);
    cudaGetSymbolAddress((void**)&w3_hi,  g_w3_hi);    cudaGetSymbolAddress((void**)&w3_lo,  g_w3_lo);

    cudaFuncSetAttribute((const void*)gemm2_bf16x3,
                         cudaFuncAttributeMaxDynamicSharedMemorySize, GEMM2_SMEM);
    cudaFuncSetAttribute((const void*)ret_contrib,
                         cudaFuncAttributeMaxDynamicSharedMemorySize, RC_SMEM);
    cudaFuncSetAttribute((const void*)ret_out,
                         cudaFuncAttributeMaxDynamicSharedMemorySize, RO_SMEM);

    // fork side stream for weight packing (independent of activations)
    cudaEventRecord(g_aux.ev0, 0);
    cudaStreamWaitEvent(g_aux.s2, g_aux.ev0, 0);
    conv_qkvg<<<4096, 256, 0, g_aux.s2>>>(wq, wk, wv, wg, wp_hi, wp_lo);
    cudaEventRecord(g_aux.evA, g_aux.s2);
    conv_wo<<<2048, 256, 0, g_aux.s2>>>(wo, wo_hi, wo_lo);
    conv_w12<<<4096, 256, 0, g_aux.s2>>>(w1, w2, w12_hi, w12_lo);
    conv_w3<<<2048, 256, 0, g_aux.s2>>>(w3, w3_hi, w3_lo);
    cudaEventRecord(g_aux.evB, g_aux.s2);

    // main stream
    ln_kernel<<<BSROWS, 256>>>(x, n1w, n1b, h_hi, h_lo);
    cudaStreamWaitEvent(0, g_aux.evA, 0);   // need packed qkvg weights

    gemm2_bf16x3<<<dim3(QST / 128, BSROWS / 128), 256, GEMM2_SMEM>>>(
        h_hi, h_lo, wp_hi, wp_lo, nullptr, qkvg, nullptr, nullptr, QST, DM);

    ret_contrib<<<dim3(NCH, NB * NH), 256, RC_SMEM>>>(qkvg + 2048, qkvg + 4096, cs);
    ret_scan<<<NB * NH, 512>>>(cs);
    ret_out<<<dim3(NCH, NB * NH), 256, RO_SMEM>>>(
        qkvg, qkvg + 2048, qkvg + 4096, cs, qkvg, a_hi, a_lo);

    cudaStreamWaitEvent(0, g_aux.evB, 0);   // need wo/w12/w3 packed weights

    gemm2_bf16x3<<<dim3(DM / 128, BSROWS / 128), 256, GEMM2_SMEM>>>(
        a_hi, a_lo, wo_hi, wo_lo, x, x1, nullptr, nullptr, DM, DM);

    ln_kernel<<<BSROWS, 256>>>(x1, n2w, n2b, h2_hi, h2_lo);

    gemm2_bf16x3<<<dim3(FST / 128, BSROWS / 128), 256, GEMM2_SMEM>>>(
        h2_hi, h2_lo, w12_hi, w12_lo, nullptr, nullptr, fg_hi, fg_lo, FST, DM);

    gemm2_bf16x3<<<dim3(DM / 128, BSROWS / 128), 256, GEMM2_SMEM>>>(
        fg_hi, fg_lo, w3_hi, w3_lo, x1, out, nullptr, nullptr, DM, HIDP);
}

// round 16
// speedup vs baseline: 1.0670x; 1.0267x over previous
#include <cuda_runtime.h>
#include <cuda_bf16.h>
#include <cstdint>
#include <cstddef>

#define NB 2
#define SL 2048
#define DM 2048
#define NH 16
#define DH 128
#define HIDN 5461
#define HIDP 5504
#define BSROWS (NB*SL)      // 4096
#define NCH 32
#define QST 8192            // packed qkvg row stride
#define FST 11008           // packed interleaved w1|w2 col count (64-blocks)

typedef __nv_bfloat16 bf16;

// ---------------- scratch ----------------
__device__ float g_qkvg[(size_t)BSROWS*QST];
__device__ float g_x1[(size_t)BSROWS*DM];
__device__ float g_st[(size_t)NB*NH*NCH*DH*DH];

__device__ __align__(16) bf16 g_h_hi [(size_t)BSROWS*DM];
__device__ __align__(16) bf16 g_h_lo [(size_t)BSROWS*DM];
__device__ __align__(16) bf16 g_h2_hi[(size_t)BSROWS*DM];
__device__ __align__(16) bf16 g_h2_lo[(size_t)BSROWS*DM];
__device__ __align__(16) bf16 g_a_hi [(size_t)BSROWS*DM];
__device__ __align__(16) bf16 g_a_lo [(size_t)BSROWS*DM];
__device__ __align__(16) bf16 g_fg_hi[(size_t)BSROWS*HIDP];
__device__ __align__(16) bf16 g_fg_lo[(size_t)BSROWS*HIDP];

__device__ __align__(16) bf16 g_wqkvg_hi[(size_t)DM*QST], g_wqkvg_lo[(size_t)DM*QST];
__device__ __align__(16) bf16 g_wo_hi[(size_t)DM*DM],  g_wo_lo[(size_t)DM*DM];
__device__ __align__(16) bf16 g_w12_hi[(size_t)DM*FST], g_w12_lo[(size_t)DM*FST];
__device__ __align__(16) bf16 g_w3_hi[(size_t)HIDP*DM], g_w3_lo[(size_t)HIDP*DM];

// ---------------- side-stream aux (host objects only; created at load) ------
namespace {
struct Aux {
    cudaStream_t s2;
    cudaEvent_t ev0, evA, evB, evKV, evSC;
    Aux() {
        cudaStreamCreateWithFlags(&s2, cudaStreamNonBlocking);
        cudaEventCreateWithFlags(&ev0,  cudaEventDisableTiming);
        cudaEventCreateWithFlags(&evA,  cudaEventDisableTiming);
        cudaEventCreateWithFlags(&evB,  cudaEventDisableTiming);
        cudaEventCreateWithFlags(&evKV, cudaEventDisableTiming);
        cudaEventCreateWithFlags(&evSC, cudaEventDisableTiming);
    }
};
Aux g_aux;
}

// ---------------- helpers ----------------
__device__ __forceinline__ unsigned f2tf(float x) {
    unsigned r;
    asm("cvt.rna.tf32.f32 %0, %1;" : "=r"(r) : "f"(x));
    return r;
}

__device__ __forceinline__ void split_bf16(float x, bf16& hi, bf16& lo) {
    hi = __float2bfloat16(x);
    lo = __float2bfloat16(x - __bfloat162float(hi));
}

__device__ __forceinline__ void split8_store(const float* v, bf16* hip, bf16* lop) {
    bf16 hh[8], ll[8];
#pragma unroll
    for (int j = 0; j < 8; j++) split_bf16(v[j], hh[j], ll[j]);
    *reinterpret_cast<uint4*>(hip) = *reinterpret_cast<uint4*>(hh);
    *reinterpret_cast<uint4*>(lop) = *reinterpret_cast<uint4*>(ll);
}

__device__ __forceinline__ void split4_store(const float* v, bf16* hip, bf16* lop) {
    bf16 hh[4], ll[4];
#pragma unroll
    for (int j = 0; j < 4; j++) split_bf16(v[j], hh[j], ll[j]);
    *reinterpret_cast<uint2*>(hip) = *reinterpret_cast<uint2*>(hh);
    *reinterpret_cast<uint2*>(lop) = *reinterpret_cast<uint2*>(ll);
}

__device__ __forceinline__ void mma8(float* c, const unsigned* a, const unsigned* b) {
    asm volatile(
        "mma.sync.aligned.m16n8k8.row.col.f32.tf32.tf32.f32 "
        "{%0,%1,%2,%3}, {%4,%5,%6,%7}, {%8,%9}, {%0,%1,%2,%3};\n"
        : "+f"(c[0]), "+f"(c[1]), "+f"(c[2]), "+f"(c[3])
        : "r"(a[0]), "r"(a[1]), "r"(a[2]), "r"(a[3]), "r"(b[0]), "r"(b[1]));
}

__device__ __forceinline__ void mma16(float* c, const unsigned* a, const unsigned* b) {
    asm volatile(
        "mma.sync.aligned.m16n8k16.row.col.f32.bf16.bf16.f32 "
        "{%0,%1,%2,%3}, {%4,%5,%6,%7}, {%8,%9}, {%0,%1,%2,%3};\n"
        : "+f"(c[0]), "+f"(c[1]), "+f"(c[2]), "+f"(c[3])
        : "r"(a[0]), "r"(a[1]), "r"(a[2]), "r"(a[3]), "r"(b[0]), "r"(b[1]));
}

__device__ __forceinline__ void ldsm4(unsigned* r, unsigned addr) {
    asm volatile("ldmatrix.sync.aligned.m8n8.x4.shared.b16 {%0,%1,%2,%3}, [%4];\n"
        : "=r"(r[0]), "=r"(r[1]), "=r"(r[2]), "=r"(r[3]) : "r"(addr));
}
__device__ __forceinline__ void ldsm4t(unsigned* r, unsigned addr) {
    asm volatile("ldmatrix.sync.aligned.m8n8.x4.trans.shared.b16 {%0,%1,%2,%3}, [%4];\n"
        : "=r"(r[0]), "=r"(r[1]), "=r"(r[2]), "=r"(r[3]) : "r"(addr));
}
__device__ __forceinline__ void cpa16(unsigned dst, const void* src) {
    asm volatile("cp.async.cg.shared.global [%0], [%1], 16;\n" :: "r"(dst), "l"(src));
}

// ---------------- weight packers ----------------
__global__ __launch_bounds__(256)
void conv_qkvg(const float* __restrict__ wq, const float* __restrict__ wk,
               const float* __restrict__ wv, const float* __restrict__ wg,
               bf16* __restrict__ hi, bf16* __restrict__ lo)
{
    const size_t n8 = (size_t)DM * QST / 8;
    size_t i = (size_t)blockIdx.x * 256 + threadIdx.x;
    const size_t st = (size_t)gridDim.x * 256;
    for (; i < n8; i += st) {
        size_t i8 = i * 8;
        size_t k = i8 >> 13;
        int c = (int)(i8 & (QST - 1));
        int proj = c >> 11, col = c & 2047;
        const float* s = (proj == 0) ? wq : (proj == 1) ? wk : (proj == 2) ? wv : wg;
        float v[8];
        *reinterpret_cast<float4*>(v)     = *reinterpret_cast<const float4*>(s + k * DM + col);
        *reinterpret_cast<float4*>(v + 4) = *reinterpret_cast<const float4*>(s + k * DM + col + 4);
        split8_store(v, hi + i8, lo + i8);
    }
}

__global__ __launch_bounds__(256)
void conv_wo(const float* __restrict__ src, bf16* __restrict__ hi, bf16* __restrict__ lo)
{
    const size_t n8 = (size_t)DM * DM / 8;
    size_t i = (size_t)blockIdx.x * 256 + threadIdx.x;
    const size_t st = (size_t)gridDim.x * 256;
    for (; i < n8; i += st) {
        size_t i8 = i * 8;
        float v[8];
        *reinterpret_cast<float4*>(v)     = *reinterpret_cast<const float4*>(src + i8);
        *reinterpret_cast<float4*>(v + 4) = *reinterpret_cast<const float4*>(src + i8 + 4);
        split8_store(v, hi + i8, lo + i8);
    }
}

// interleaved at 64-col granularity: 64-col blocks alternate w1/w2.
__global__ __launch_bounds__(256)
void conv_w12(const float* __restrict__ w1, const float* __restrict__ w2,
              bf16* __restrict__ hi, bf16* __restrict__ lo)
{
    const size_t n8 = (size_t)DM * FST / 8;
    size_t i = (size_t)blockIdx.x * 256 + threadIdx.x;
    const size_t st = (size_t)gridDim.x * 256;
    for (; i < n8; i += st) {
        size_t i8 = i * 8;
        size_t k = i8 / FST;
        int c = (int)(i8 - k * FST);
        int blk = c >> 6;
        int fcol = (blk >> 1) * 64 + (c & 63);
        const float* w = (blk & 1) ? w2 : w1;
        float v[8];
#pragma unroll
        for (int j = 0; j < 8; j++) {
            int col = fcol + j;
            v[j] = (col < HIDN) ? w[k * HIDN + col] : 0.f;
        }
        split8_store(v, hi + i8, lo + i8);
    }
}

__global__ __launch_bounds__(256)
void conv_w3(const float* __restrict__ w3, bf16* __restrict__ hi, bf16* __restrict__ lo)
{
    const size_t n8 = (size_t)HIDP * DM / 8;
    size_t i = (size_t)blockIdx.x * 256 + threadIdx.x;
    const size_t st = (size_t)gridDim.x * 256;
    for (; i < n8; i += st) {
        size_t i8 = i * 8;
        int r = (int)(i8 >> 11);
        float v[8];
        if (r < HIDN) {
            *reinterpret_cast<float4*>(v)     = *reinterpret_cast<const float4*>(w3 + i8);
            *reinterpret_cast<float4*>(v + 4) = *reinterpret_cast<const float4*>(w3 + i8 + 4);
        } else {
#pragma unroll
            for (int j = 0; j < 8; j++) v[j] = 0.f;
        }
        split8_store(v, hi + i8, lo + i8);
    }
}

// ---------------- LayerNorm -> bf16 hi/lo ----------------
__global__ __launch_bounds__(256)
void ln_kernel(const float* __restrict__ x, const float* __restrict__ w,
               const float* __restrict__ b, bf16* __restrict__ ohi,
               bf16* __restrict__ olo)
{
    __shared__ float red[16];
    const int row = blockIdx.x;
    const float* xr = x + (size_t)row * DM;
    float vals[8];
    float s = 0.f, ss = 0.f;
#pragma unroll
    for (int j = 0; j < 8; j++) {
        float v = xr[threadIdx.x + j * 256];
        vals[j] = v; s += v; ss += v * v;
    }
#pragma unroll
    for (int o = 16; o > 0; o >>= 1) {
        s  += __shfl_xor_sync(0xFFFFFFFFu, s,  o);
        ss += __shfl_xor_sync(0xFFFFFFFFu, ss, o);
    }
    const int warp = threadIdx.x >> 5, lane = threadIdx.x & 31;
    if (lane == 0) { red[warp] = s; red[8 + warp] = ss; }
    __syncthreads();
    s = 0.f; ss = 0.f;
#pragma unroll
    for (int k = 0; k < 8; k++) { s += red[k]; ss += red[8 + k]; }
    const float mean = s * (1.f / DM);
    const float var  = ss * (1.f / DM) - mean * mean;
    const float rstd = rsqrtf(var + 1e-5f);
#pragma unroll
    for (int j = 0; j < 8; j++) {
        int col = threadIdx.x + j * 256;
        float o = (vals[j] - mean) * rstd * w[col] + b[col];
        split_bf16(o, ohi[(size_t)row * DM + col], olo[(size_t)row * DM + col]);
    }
}

// ---------------- bf16x3 GEMM: CTA 128x128, 3-stage, 2 CTAs/SM ----------------
#define STG2_B 37888u
#define OFF2_AL 10240u
#define OFF2_BH 20480u
#define OFF2_BL 29184u
#define NSTG2 3u
#define GEMM2_SMEM (NSTG2*STG2_B)   // 113664 -> 2 CTAs = 227328 <= 228KB
#define EP2_LD 132                  // gated epilogue smem row stride (floats)

__global__ __launch_bounds__(256, 2)
void gemm2_bf16x3(const bf16* __restrict__ Ahi, const bf16* __restrict__ Alo,
                  const bf16* __restrict__ Bhi, const bf16* __restrict__ Blo,
                  const float* __restrict__ Res, float* __restrict__ C,
                  bf16* __restrict__ Ghi, bf16* __restrict__ Glo,
                  int N, int K)
{
    extern __shared__ __align__(16) char smemraw[];
    const unsigned s0 = (unsigned)__cvta_generic_to_shared(smemraw);

    const int tid  = threadIdx.x;
    const int lane = tid & 31;
    const int warp = tid >> 5;
    const int wm = warp >> 2;     // 0..1 : 64 rows
    const int wn = warp & 3;      // 0..3 : 32 cols
    const int bm = blockIdx.y * 128;
    const int bn = blockIdx.x * 128;

    // pointer-increment prefetch state (computed once)
    const int arow = tid >> 2, achn = tid & 3;
    const int brow = tid >> 4, bchn = tid & 15;
    const bf16* pAh = Ahi + (size_t)(bm + arow) * K + achn * 8;
    const bf16* pAl = Alo + (size_t)(bm + arow) * K + achn * 8;
    const bf16* pBh = Bhi + (size_t)brow * N + bn + bchn * 8;
    const bf16* pBl = Blo + (size_t)brow * N + bn + bchn * 8;
    const size_t aStep = 64 * (size_t)K;    // second A chunk (row +64)
    const size_t bStep = 16 * (size_t)N;    // second B chunk (row +16)
    const size_t bAdv  = 32 * (size_t)N;    // per-stage B advance
    const unsigned soA = (unsigned)(arow * 80 + achn * 16);
    const unsigned soB = (unsigned)(brow * 272 + bchn * 16);

#define G2_PREFETCH(stg)                                           \
    do {                                                           \
        unsigned _s = (stg);                                       \
        cpa16(_s + soA,              pAh);                         \
        cpa16(_s + soA + 5120u,      pAh + aStep);                 \
        cpa16(_s + OFF2_AL + soA,         pAl);                    \
        cpa16(_s + OFF2_AL + soA + 5120u, pAl + aStep);            \
        cpa16(_s + OFF2_BH + soB,         pBh);                    \
        cpa16(_s + OFF2_BH + soB + 4352u, pBh + bStep);            \
        cpa16(_s + OFF2_BL + soB,         pBl);                    \
        cpa16(_s + OFF2_BL + soB + 4352u, pBl + bStep);            \
        asm volatile("cp.async.commit_group;\n" ::: "memory");     \
        pAh += 32; pAl += 32; pBh += bAdv; pBl += bAdv;            \
    } while (0)

    const unsigned laneA = (unsigned)(((lane & 7) + ((lane >> 3) & 1) * 8) * 80 + (lane >> 4) * 16);
    const unsigned laneB = (unsigned)(((lane & 7) + ((lane >> 3) & 1) * 8) * 272 + (lane >> 4) * 16);

    float acc[4][4][4];
#pragma unroll
    for (int a = 0; a < 4; a++)
#pragma unroll
        for (int b = 0; b < 4; b++)
#pragma unroll
            for (int c = 0; c < 4; c++) acc[a][b][c] = 0.f;

    const int nk = K >> 5;
    G2_PREFETCH(s0);
    G2_PREFETCH(s0 + STG2_B);

    unsigned stage = 0;
    for (int t = 0; t < nk; t++) {
        if (t + 1 < nk) asm volatile("cp.async.wait_group 1;\n" ::: "memory");
        else            asm volatile("cp.async.wait_group 0;\n" ::: "memory");
        __syncthreads();

        if (t + 2 < nk) {
            unsigned nst = stage + 2u * STG2_B;
            if (nst >= NSTG2 * STG2_B) nst -= NSTG2 * STG2_B;
            G2_PREFETCH(s0 + nst);
        }

        const unsigned st = s0 + stage;
        const unsigned aBase = st + (unsigned)(wm * 64 * 80) + laneA;
        const unsigned bBase = st + OFF2_BH + (unsigned)(wn * 32 * 2) + laneB;

#pragma unroll
        for (int ks = 0; ks < 2; ks++) {
            unsigned ah[4][4], al[4][4];
#pragma unroll
            for (int mt = 0; mt < 4; mt++) {
                unsigned ad = aBase + (unsigned)(mt * 16 * 80 + ks * 32);
                ldsm4(ah[mt], ad);
                ldsm4(al[mt], ad + OFF2_AL);
            }
#pragma unroll
            for (int p = 0; p < 2; p++) {
                unsigned bh[4], bl[4];
                unsigned bd = bBase + (unsigned)(ks * 16 * 272 + p * 32);
                ldsm4t(bh, bd);
                ldsm4t(bl, bd + (OFF2_BL - OFF2_BH));
#pragma unroll
                for (int mt = 0; mt < 4; mt++) {
                    mma16(acc[mt][2*p],   ah[mt], bh);
                    mma16(acc[mt][2*p],   ah[mt], bl);
                    mma16(acc[mt][2*p],   al[mt], bh);
                    mma16(acc[mt][2*p+1], ah[mt], bh + 2);
                    mma16(acc[mt][2*p+1], ah[mt], bl + 2);
                    mma16(acc[mt][2*p+1], al[mt], bh + 2);
                }
            }
        }
        stage += STG2_B;
        if (stage >= NSTG2 * STG2_B) stage = 0;
    }
#undef G2_PREFETCH

    if (Ghi) {
        // gated epilogue: tile cols [0,64)=f1, [64,128)=f2 (same f-col range)
        __syncthreads();
        float* SM = reinterpret_cast<float*>(smemraw);
#pragma unroll
        for (int mt = 0; mt < 4; mt++)
#pragma unroll
            for (int nt = 0; nt < 4; nt++) {
                int r0 = wm * 64 + mt * 16 + (lane >> 2);
                int c0 = wn * 32 + nt * 8 + (lane & 3) * 2;
#pragma unroll
                for (int half = 0; half < 2; half++) {
                    int r = r0 + half * 8;
                    SM[r * EP2_LD + c0]     = acc[mt][nt][half * 2];
                    SM[r * EP2_LD + c0 + 1] = acc[mt][nt][half * 2 + 1];
                }
            }
        __syncthreads();
        const int fcol0 = blockIdx.x * 64;
#pragma unroll
        for (int j = 0; j < 4; j++) {
            int idx8 = (tid + j * 256) * 8;   // 128 rows x 64 f-cols
            int row = idx8 >> 6, c = idx8 & 63;
            const float* p1 = SM + row * EP2_LD + c;
            const float* p2 = p1 + 64;
            float v[8];
#pragma unroll
            for (int e = 0; e < 8; e++) {
                float a = p1[e];
                v[e] = (a / (1.f + expf(-a))) * p2[e];
            }
            size_t go = (size_t)(bm + row) * HIDP + fcol0 + c;
            split8_store(v, Ghi + go, Glo + go);
        }
    } else {
#pragma unroll
        for (int mt = 0; mt < 4; mt++)
#pragma unroll
            for (int nt = 0; nt < 4; nt++) {
                int r0 = bm + wm * 64 + mt * 16 + (lane >> 2);
                int c0 = bn + wn * 32 + nt * 8 + (lane & 3) * 2;
#pragma unroll
                for (int half = 0; half < 2; half++) {
                    int r = r0 + half * 8;
                    float2 v = make_float2(acc[mt][nt][half * 2], acc[mt][nt][half * 2 + 1]);
                    if (Res) {
                        float2 rv = *reinterpret_cast<const float2*>(&Res[(size_t)r * N + c0]);
                        v.x += rv.x; v.y += rv.y;
                    }
                    *reinterpret_cast<float2*>(&C[(size_t)r * N + c0]) = v;
                }
            }
    }
}

// ================= chunkwise retention =================
#define RC_SMEM ((128*68 + 64*136)*4)

__global__ __launch_bounds__(256, 1)
void ret_contrib(const float* __restrict__ K, const float* __restrict__ V,
                 float* __restrict__ CS)
{
    extern __shared__ float smc[];
    float* KsT = smc;
    float* Vs  = KsT + 128 * 68;

    const int tid  = threadIdx.x;
    const int lane = tid & 31;
    const int warp = tid >> 5;
    const int gq = lane >> 2;
    const int tg = lane & 3;
    const int wm = warp >> 2;
    const int wn = warp & 3;
    const int chunk = blockIdx.x;
    const int bh = blockIdx.y;
    const int b = bh >> 4, h = bh & 15;
    const int kb = chunk * 64;

    const float gamma = 1.f - exp2f(-5.f - (float)h);
    const float lg = log2f(gamma);
    const size_t rowbase = (size_t)(b * SL) * QST + (size_t)h * DH;

#pragma unroll
    for (int it = 0; it < 32; it++) {
        int idx = tid + it * 256;
        int t = idx >> 7, d = idx & 127;
        size_t gidx = rowbase + (size_t)(kb + t) * QST + d;
        float w = 0.08838834764831845f * exp2f((float)(63 - t) * lg);
        KsT[d * 68 + t] = __uint_as_float(f2tf(w * K[gidx]));
        Vs[t * 136 + d] = __uint_as_float(f2tf(V[gidx]));
    }
    __syncthreads();

    float acc[4][4][4];
#pragma unroll
    for (int a = 0; a < 4; a++)
#pragma unroll
        for (int bq = 0; bq < 4; bq++)
#pragma unroll
            for (int c = 0; c < 4; c++) acc[a][bq][c] = 0.f;

#pragma unroll
    for (int ks = 0; ks < 8; ks++) {
        const int kkk = ks * 8;
        unsigned af[4][4], bf[4][2];
#pragma unroll
        for (int mt = 0; mt < 4; mt++) {
            int m = wm * 64 + mt * 16 + gq;
            af[mt][0] = __float_as_uint(KsT[m * 68 + kkk + tg]);
            af[mt][1] = __float_as_uint(KsT[(m + 8) * 68 + kkk + tg]);
            af[mt][2] = __float_as_uint(KsT[m * 68 + kkk + tg + 4]);
            af[mt][3] = __float_as_uint(KsT[(m + 8) * 68 + kkk + tg + 4]);
        }
#pragma unroll
        for (int nt = 0; nt < 4; nt++) {
            int n = wn * 32 + nt * 8 + gq;
            bf[nt][0] = __float_as_uint(Vs[(kkk + tg) * 136 + n]);
            bf[nt][1] = __float_as_uint(Vs[(kkk + tg + 4) * 136 + n]);
        }
#pragma unroll
        for (int mt = 0; mt < 4; mt++)
#pragma unroll
            for (int nt = 0; nt < 4; nt++)
                mma8(acc[mt][nt], af[mt], bf[nt]);
    }

    float* outp = CS + ((size_t)bh * NCH + chunk) * (DH * DH);
#pragma unroll
    for (int mt = 0; mt < 4; mt++)
#pragma unroll
        for (int nt = 0; nt < 4; nt++) {
            int r0 = wm * 64 + mt * 16 + gq;
            int c0 = wn * 32 + nt * 8 + tg * 2;
#pragma unroll
            for (int e = 0; e < 4; e++) {
                int r = r0 + (e >> 1) * 8;
                int c = c0 + (e & 1);
                outp[r * DH + c] = acc[mt][nt][e];
            }
        }
}

__global__ __launch_bounds__(512)
void ret_scan(float* __restrict__ CS)
{
    const int bh = blockIdx.x;
    const int h = bh & 15;
    const float gamma = 1.f - exp2f(-5.f - (float)h);
    const float dec = exp2f(64.f * log2f(gamma));
    float* base = CS + (size_t)bh * NCH * (DH * DH);
    const int tid = threadIdx.x;

    float s[32];
#pragma unroll
    for (int j = 0; j < 32; j++) s[j] = 0.f;
    for (int i = 0; i < NCH; i++) {
        float* p = base + (size_t)i * (DH * DH);
#pragma unroll
        for (int j = 0; j < 32; j++) {
            int e = tid + j * 512;
            float c = p[e];
            p[e] = s[j];
            s[j] = s[j] * dec + c;
        }
    }
}

// ret_out with fused per-head GroupNorm + silu gate epilogue -> a_hi/a_lo (bf16)
#define RO_SMEM ((64*132*2 + 64*136 + 64*68 + 128*136 + 128 + 64)*4)

__global__ __launch_bounds__(256, 1)
void ret_out(const float* __restrict__ Q, const float* __restrict__ Kt,
             const float* __restrict__ V, const float* __restrict__ CS,
             const float* __restrict__ QKVG,
             bf16* __restrict__ Ahi, bf16* __restrict__ Alo)
{
    extern __shared__ float smr[];
    float* Qs  = smr;                // [64][132] (reused as output stage)
    float* Ks  = Qs + 64 * 132;
    float* Vs  = Ks + 64 * 132;
    float* Ss  = Vs + 64 * 136;
    float* Sts = Ss + 64 * 68;
    float* dp  = Sts + 128 * 136;
    float* dp2 = dp + 128;

    const int tid  = threadIdx.x;
    const int lane = tid & 31;
    const int warp = tid >> 5;
    const int gq = lane >> 2;
    const int tg = lane & 3;
    const int wm = warp >> 2;
    const int wn = warp & 3;
    const int chunk = blockIdx.x;
    const int bh = blockIdx.y;
    const int b = bh >> 4, h = bh & 15;
    const int qb = chunk * 64;

    const float gamma = 1.f - exp2f(-5.f - (float)h);
    const float lg = log2f(gamma);
    const size_t rowbase = (size_t)(b * SL) * QST + (size_t)h * DH;
    const float* stp = CS + ((size_t)bh * NCH + chunk) * (DH * DH);

#pragma unroll
    for (int it = 0; it < 32; it++) {
        int idx = tid + it * 256;
        int r = idx >> 7, d = idx & 127;
        size_t gidx = rowbase + (size_t)(qb + r) * QST + d;
        Qs[r * 132 + d] = __uint_as_float(f2tf(Q[gidx]));
        Ks[r * 132 + d] = __uint_as_float(f2tf(Kt[gidx]));
        Vs[r * 136 + d] = __uint_as_float(f2tf(V[gidx]));
    }
#pragma unroll
    for (int it = 0; it < 64; it++) {
        int idx = tid + it * 256;
        int r = idx >> 7, d = idx & 127;
        Sts[r * 136 + d] = __uint_as_float(f2tf(stp[idx]));
    }
    if (tid < 128) {
        int e = tid - 63;
        dp[tid] = (e < 0) ? 0.f : 0.08838834764831845f * exp2f((float)e * lg);
    }
    if (tid < 64) dp2[tid] = exp2f((float)(tid + 1) * lg);
    __syncthreads();

    float acco[2][4][4];
#pragma unroll
    for (int a = 0; a < 2; a++)
#pragma unroll
        for (int bq = 0; bq < 4; bq++)
#pragma unroll
            for (int c = 0; c < 4; c++) acco[a][bq][c] = 0.f;

#pragma unroll
    for (int ks = 0; ks < 16; ks++) {
        const int kkk = ks * 8;
        unsigned af[2][4], bf[4][2];
#pragma unroll
        for (int mt = 0; mt < 2; mt++) {
            int m = wm * 32 + mt * 16 + gq;
            af[mt][0] = __float_as_uint(Qs[m * 132 + kkk + tg]);
            af[mt][1] = __float_as_uint(Qs[(m + 8) * 132 + kkk + tg]);
            af[mt][2] = __float_as_uint(Qs[m * 132 + kkk + tg + 4]);
            af[mt][3] = __float_as_uint(Qs[(m + 8) * 132 + kkk + tg + 4]);
        }
#pragma unroll
        for (int nt = 0; nt < 4; nt++) {
            int n = wn * 32 + nt * 8 + gq;
            bf[nt][0] = __float_as_uint(Sts[(kkk + tg) * 136 + n]);
            bf[nt][1] = __float_as_uint(Sts[(kkk + tg + 4) * 136 + n]);
        }
#pragma unroll
        for (int mt = 0; mt < 2; mt++)
#pragma unroll
            for (int nt = 0; nt < 4; nt++)
                mma8(acco[mt][nt], af[mt], bf[nt]);
    }
#pragma unroll
    for (int mt = 0; mt < 2; mt++) {
        int r0 = wm * 32 + mt * 16 + gq;
        float sc0 = dp2[r0], sc1 = dp2[r0 + 8];
#pragma unroll
        for (int nt = 0; nt < 4; nt++) {
            acco[mt][nt][0] *= sc0; acco[mt][nt][1] *= sc0;
            acco[mt][nt][2] *= sc1; acco[mt][nt][3] *= sc1;
        }
    }

    float accs[2][2][4];
#pragma unroll
    for (int a = 0; a < 2; a++)
#pragma unroll
        for (int bq = 0; bq < 2; bq++)
#pragma unroll
            for (int c = 0; c < 4; c++) accs[a][bq][c] = 0.f;
#pragma unroll
    for (int ks = 0; ks < 16; ks++) {
        const int kkk = ks * 8;
        unsigned af[2][4], bf[2][2];
#pragma unroll
        for (int mt = 0; mt < 2; mt++) {
            int m = wm * 32 + mt * 16 + gq;
            af[mt][0] = __float_as_uint(Qs[m * 132 + kkk + tg]);
            af[mt][1] = __float_as_uint(Qs[(m + 8) * 132 + kkk + tg]);
            af[mt][2] = __float_as_uint(Qs[m * 132 + kkk + tg + 4]);
            af[mt][3] = __float_as_uint(Qs[(m + 8) * 132 + kkk + tg + 4]);
        }
#pragma unroll
        for (int nt = 0; nt < 2; nt++) {
            int n = wn * 16 + nt * 8 + gq;
            bf[nt][0] = __float_as_uint(Ks[n * 132 + kkk + tg]);
            bf[nt][1] = __float_as_uint(Ks[n * 132 + kkk + tg + 4]);
        }
#pragma unroll
        for (int mt = 0; mt < 2; mt++)
#pragma unroll
            for (int nt = 0; nt < 2; nt++)
                mma8(accs[mt][nt], af[mt], bf[nt]);
    }
#pragma unroll
    for (int mt = 0; mt < 2; mt++)
#pragma unroll
        for (int nt = 0; nt < 2; nt++) {
            int sr0 = wm * 32 + mt * 16 + gq;
            int tc0 = wn * 16 + nt * 8 + tg * 2;
#pragma unroll
            for (int e = 0; e < 4; e++) {
                int sr = sr0 + (e >> 1) * 8;
                int tc = tc0 + (e & 1);
                float coeff = dp[sr - tc + 63];
                Ss[sr * 68 + tc] = __uint_as_float(f2tf(accs[mt][nt][e] * coeff));
            }
        }
    __syncthreads();

#pragma unroll
    for (int ks = 0; ks < 8; ks++) {
        const int kkk = ks * 8;
        unsigned af[2][4], bf[4][2];
#pragma unroll
        for (int mt = 0; mt < 2; mt++) {
            int m = wm * 32 + mt * 16 + gq;
            af[mt][0] = __float_as_uint(Ss[m * 68 + kkk + tg]);
            af[mt][1] = __float_as_uint(Ss[(m + 8) * 68 + kkk + tg]);
            af[mt][2] = __float_as_uint(Ss[m * 68 + kkk + tg + 4]);
            af[mt][3] = __float_as_uint(Ss[(m + 8) * 68 + kkk + tg + 4]);
        }
#pragma unroll
        for (int nt = 0; nt < 4; nt++) {
            int n = wn * 32 + nt * 8 + gq;
            bf[nt][0] = __float_as_uint(Vs[(kkk + tg) * 136 + n]);
            bf[nt][1] = __float_as_uint(Vs[(kkk + tg + 4) * 136 + n]);
        }
#pragma unroll
        for (int mt = 0; mt < 2; mt++)
#pragma unroll
            for (int nt = 0; nt < 4; nt++)
                mma8(acco[mt][nt], af[mt], bf[nt]);
    }

    // ---- fused epilogue: stage to smem, per-row groupnorm + silu gate -> bf16 hi/lo
    __syncthreads();   // all warps done reading Qs (OS aliases Qs)
    float* OS = Qs;    // [64][132]
#pragma unroll
    for (int mt = 0; mt < 2; mt++)
#pragma unroll
        for (int nt = 0; nt < 4; nt++) {
            int r0 = wm * 32 + mt * 16 + gq;
            int c0 = wn * 32 + nt * 8 + tg * 2;
#pragma unroll
            for (int e = 0; e < 4; e++) {
                int r = r0 + (e >> 1) * 8;
                int c = c0 + (e & 1);
                OS[r * 132 + c] = acco[mt][nt][e];
            }
        }
    __syncthreads();

#pragma unroll
    for (int i = 0; i < 8; i++) {
        int row = warp + i * 8;       // local row 0..63, one warp per row
        float4 v = *reinterpret_cast<const float4*>(OS + row * 132 + lane * 4);
        float s  = v.x + v.y + v.z + v.w;
        float ss = v.x*v.x + v.y*v.y + v.z*v.z + v.w*v.w;
#pragma unroll
        for (int o = 16; o > 0; o >>= 1) {
            s  += __shfl_xor_sync(0xFFFFFFFFu, s,  o);
            ss += __shfl_xor_sync(0xFFFFFFFFu, ss, o);
        }
        const float mean = s * (1.f / DH);
        const float var  = ss * (1.f / DH) - mean * mean;
        const float rstd = rsqrtf(var + 1e-5f);
        const int grow = b * SL + qb + row;
        float4 gv = *reinterpret_cast<const float4*>(
            QKVG + (size_t)grow * QST + 6144 + h * DH + lane * 4);
        float outv[4];
        outv[0] = (gv.x / (1.f + expf(-gv.x))) * ((v.x - mean) * rstd);
        outv[1] = (gv.y / (1.f + expf(-gv.y))) * ((v.y - mean) * rstd);
        outv[2] = (gv.z / (1.f + expf(-gv.z))) * ((v.z - mean) * rstd);
        outv[3] = (gv.w / (1.f + expf(-gv.w))) * ((v.w - mean) * rstd);
        size_t ab = (size_t)grow * DM + h * DH + lane * 4;
        split4_store(outv, Ahi + ab, Alo + ab);
    }
}

// ---------------- launch ----------------
extern "C" void kernel_launch(void* const* d_in, const int* in_sizes, int n_in,
                              void* d_out, int out_size)
{
    const float* x   = (const float*)d_in[0];
    const float* n1w = (const float*)d_in[1];
    const float* n1b = (const float*)d_in[2];
    const float* wq  = (const float*)d_in[3];
    const float* wk  = (const float*)d_in[4];
    const float* wv  = (const float*)d_in[5];
    const float* wg  = (const float*)d_in[6];
    const float* wo  = (const float*)d_in[7];
    const float* n2w = (const float*)d_in[8];
    const float* n2b = (const float*)d_in[9];
    const float* w1  = (const float*)d_in[10];
    const float* w2  = (const float*)d_in[11];
    const float* w3  = (const float*)d_in[12];
    float* out = (float*)d_out;

    float *qkvg, *x1, *cs;
    bf16 *h_hi, *h_lo, *h2_hi, *h2_lo, *a_hi, *a_lo, *fg_hi, *fg_lo;
    bf16 *wp_hi, *wp_lo, *wo_hi, *wo_lo, *w12_hi, *w12_lo, *w3_hi, *w3_lo;

    cudaGetSymbolAddress((void**)&qkvg, g_qkvg);
    cudaGetSymbolAddress((void**)&x1,   g_x1);
    cudaGetSymbolAddress((void**)&cs,   g_st);
    cudaGetSymbolAddress((void**)&h_hi,  g_h_hi);
    cudaGetSymbolAddress((void**)&h_lo,  g_h_lo);
    cudaGetSymbolAddress((void**)&h2_hi, g_h2_hi);
    cudaGetSymbolAddress((void**)&h2_lo, g_h2_lo);
    cudaGetSymbolAddress((void**)&a_hi,  g_a_hi);
    cudaGetSymbolAddress((void**)&a_lo,  g_a_lo);
    cudaGetSymbolAddress((void**)&fg_hi, g_fg_hi);
    cudaGetSymbolAddress((void**)&fg_lo, g_fg_lo);
    cudaGetSymbolAddress((void**)&wp_hi,  g_wqkvg_hi); cudaGetSymbolAddress((void**)&wp_lo,  g_wqkvg_lo);
    cudaGetSymbolAddress((void**)&wo_hi,  g_wo_hi);    cudaGetSymbolAddress((void**)&wo_lo,  g_wo_lo);
    cudaGetSymbolAddress((void**)&w12_hi, g_w12_hi);   cudaGetSymbolAddress((void**)&w12_lo, g_w12_lo);
    cudaGetSymbolAddress((void**)&w3_hi,  g_w3_hi);    cudaGetSymbolAddress((void**)&w3_lo,  g_w3_lo);

    cudaFuncSetAttribute((const void*)gemm2_bf16x3,
                         cudaFuncAttributeMaxDynamicSharedMemorySize, GEMM2_SMEM);
    cudaFuncSetAttribute((const void*)ret_contrib,
                         cudaFuncAttributeMaxDynamicSharedMemorySize, RC_SMEM);
    cudaFuncSetAttribute((const void*)ret_out,
                         cudaFuncAttributeMaxDynamicSharedMemorySize, RO_SMEM);

    // fork side stream for weight packing (independent of activations)
    cudaEventRecord(g_aux.ev0, 0);
    cudaStreamWaitEvent(g_aux.s2, g_aux.ev0, 0);
    conv_qkvg<<<4096, 256, 0, g_aux.s2>>>(wq, wk, wv, wg, wp_hi, wp_lo);
    cudaEventRecord(g_aux.evA, g_aux.s2);
    conv_wo<<<2048, 256, 0, g_aux.s2>>>(wo, wo_hi, wo_lo);
    conv_w12<<<4096, 256, 0, g_aux.s2>>>(w1, w2, w12_hi, w12_lo);
    conv_w3<<<2048, 256, 0, g_aux.s2>>>(w3, w3_hi, w3_lo);
    cudaEventRecord(g_aux.evB, g_aux.s2);

    // main stream
    ln_kernel<<<BSROWS, 256>>>(x, n1w, n1b, h_hi, h_lo);
    cudaStreamWaitEvent(0, g_aux.evA, 0);   // need packed qkvg weights

    // k,v projection first (cols 2048..6144)
    gemm2_bf16x3<<<dim3(32, BSROWS / 128), 256, GEMM2_SMEM>>>(
        h_hi, h_lo, wp_hi + 2048, wp_lo + 2048, nullptr, qkvg + 2048,
        nullptr, nullptr, QST, DM);
    cudaEventRecord(g_aux.evKV, 0);

    // q and g projections (cols 0..2048 and 6144..8192), overlapped with
    // retention-prep on the side stream
    gemm2_bf16x3<<<dim3(16, BSROWS / 128), 256, GEMM2_SMEM>>>(
        h_hi, h_lo, wp_hi, wp_lo, nullptr, qkvg, nullptr, nullptr, QST, DM);
    gemm2_bf16x3<<<dim3(16, BSROWS / 128), 256, GEMM2_SMEM>>>(
        h_hi, h_lo, wp_hi + 6144, wp_lo + 6144, nullptr, qkvg + 6144,
        nullptr, nullptr, QST, DM);

    cudaStreamWaitEvent(g_aux.s2, g_aux.evKV, 0);
    ret_contrib<<<dim3(NCH, NB * NH), 256, RC_SMEM, g_aux.s2>>>(
        qkvg + 2048, qkvg + 4096, cs);
    ret_scan<<<NB * NH, 512, 0, g_aux.s2>>>(cs);
    cudaEventRecord(g_aux.evSC, g_aux.s2);

    cudaStreamWaitEvent(0, g_aux.evSC, 0);  // scan result ready
    ret_out<<<dim3(NCH, NB * NH), 256, RO_SMEM>>>(
        qkvg, qkvg + 2048, qkvg + 4096, cs, qkvg, a_hi, a_lo);

    cudaStreamWaitEvent(0, g_aux.evB, 0);   // need wo/w12/w3 packed weights

    gemm2_bf16x3<<<dim3(DM / 128, BSROWS / 128), 256, GEMM2_SMEM>>>(
        a_hi, a_lo, wo_hi, wo_lo, x, x1, nullptr, nullptr, DM, DM);

    ln_kernel<<<BSROWS, 256>>>(x1, n2w, n2b, h2_hi, h2_lo);

    gemm2_bf16x3<<<dim3(FST / 128, BSROWS / 128), 256, GEMM2_SMEM>>>(
        h2_hi, h2_lo, w12_hi, w12_lo, nullptr, nullptr, fg_hi, fg_lo, FST, DM);

    gemm2_bf16x3<<<dim3(DM / 128, BSROWS / 128), 256, GEMM2_SMEM>>>(
        fg_hi, fg_lo, w3_hi, w3_lo, x1, out, nullptr, nullptr, DM, HIDP);
}